// round 11
// baseline (speedup 1.0000x reference)
#include <cuda_runtime.h>
#include <cuda_bf16.h>
#include <cstdint>

#define H 128
#define BM 64          // node-kernel tile
#define BE 32          // edge-kernel per-group tile
#define MAXN 50176
#define MAXE 800000

// ---------------- scratch (device globals) ----------------
__device__ float g_P[MAXN * H];
__device__ float g_Q[MAXN * H];
__device__ float g_Hsum[MAXN * H];
__device__ float g_agg[MAXN * H];
__device__ float g_Tbuf[MAXN * H];
__device__ int   g_cnt[MAXN];
__device__ int   g_row[MAXE];
__device__ int   g_col[MAXE];
__device__ __align__(16) char g_Wimg[14 * 32768];

// ---------------- smem layouts ----------------
#define ASTRIDE 272
#define ATILE   (64 * ASTRIDE)           // 17408 (node A image)
#define WTILE   (128 * ASTRIDE)          // 34816
// node layout (unchanged from R10)
#define SM_AH   0
#define SM_AL   ATILE
#define SM_WH   (2 * ATILE)
#define SM_WL   (2 * ATILE + WTILE)
#define SMEM_NODE (2 * ATILE + 2 * WTILE)        // 104448
// edge layout: shared W first, then per-group A (32 rows hi+lo) + ids
#define E_WH    0
#define E_WL    WTILE
#define E_AG    (32 * ASTRIDE)           // 8704: one 32-row image
#define E_A(g)  (2 * WTILE + (g) * 2 * E_AG)
#define E_RID(g) (2 * WTILE + 4 * E_AG + (g) * 256)
#define E_CID(g) (E_RID(g) + 128)
#define SMEM_EDGE (2 * WTILE + 4 * E_AG + 512)   // 104960

// ---------------- PTX helpers ----------------
__device__ __forceinline__ uint32_t smem_u32(const void* p) {
    uint32_t a;
    asm("{ .reg .u64 t; cvta.to.shared.u64 t, %1; cvt.u32.u64 %0, t; }" : "=r"(a) : "l"(p));
    return a;
}
__device__ __forceinline__ void ldsm_x4(uint32_t* r, uint32_t addr) {
    asm volatile("ldmatrix.sync.aligned.m8n8.x4.shared.b16 {%0,%1,%2,%3}, [%4];"
                 : "=r"(r[0]), "=r"(r[1]), "=r"(r[2]), "=r"(r[3]) : "r"(addr));
}
__device__ __forceinline__ void mma16816(float* d, const uint32_t* a, uint32_t b0, uint32_t b1) {
    asm volatile("mma.sync.aligned.m16n8k16.row.col.f32.bf16.bf16.f32 "
                 "{%0,%1,%2,%3}, {%4,%5,%6,%7}, {%8,%9}, {%0,%1,%2,%3};"
                 : "+f"(d[0]), "+f"(d[1]), "+f"(d[2]), "+f"(d[3])
                 : "r"(a[0]), "r"(a[1]), "r"(a[2]), "r"(a[3]), "r"(b0), "r"(b1));
}
__device__ __forceinline__ void red_add_v4(float* p, float4 v) {
    asm volatile("red.global.add.v4.f32 [%0], {%1,%2,%3,%4};"
                 :: "l"(p), "f"(v.x), "f"(v.y), "f"(v.z), "f"(v.w) : "memory");
}
#define BAR_G(id) asm volatile("bar.sync %0, 128;" :: "r"(id) : "memory")

__device__ __forceinline__ void split2(float a, float b, uint32_t& hi, uint32_t& lo) {
    __nv_bfloat16 ha = __float2bfloat16_rn(a), hb = __float2bfloat16_rn(b);
    float ra = a - __bfloat162float(ha), rb = b - __bfloat162float(hb);
    __nv_bfloat16 la = __float2bfloat16_rn(ra), lb = __float2bfloat16_rn(rb);
    hi = ((uint32_t)*(uint16_t*)&hb << 16) | (uint32_t)*(uint16_t*)&ha;
    lo = ((uint32_t)*(uint16_t*)&lb << 16) | (uint32_t)*(uint16_t*)&la;
}

// ---------------- node-path A/W loaders (256 threads) ----------------
__device__ __forceinline__ void load_convert_A(const float* __restrict__ A, int gm, int M,
                                               char* sm, int tid) {
#pragma unroll
    for (int it = 0; it < 8; ++it) {
        int idx = tid + it * 256;
        int m = idx >> 5;
        int k4 = (idx & 31) << 2;
        float4 v = make_float4(0.f, 0.f, 0.f, 0.f);
        int gr = gm + m;
        if (gr < M) v = *(const float4*)(A + (size_t)gr * H + k4);
        uint32_t h0, l0, h1, l1;
        split2(v.x, v.y, h0, l0);
        split2(v.z, v.w, h1, l1);
        uint32_t off = (uint32_t)m * ASTRIDE + (uint32_t)k4 * 2;
        *(uint2*)(sm + SM_AH + off) = make_uint2(h0, h1);
        *(uint2*)(sm + SM_AL + off) = make_uint2(l0, l1);
    }
}
__device__ __forceinline__ void copy_W(const char* __restrict__ wh, const char* __restrict__ wl,
                                       char* sm, int whOff, int wlOff, int tid) {
#pragma unroll
    for (int it = 0; it < 8; ++it) {
        int idx = tid + it * 256;
        int row = idx >> 4;
        int chunk = idx & 15;
        uint32_t off = (uint32_t)row * ASTRIDE + (uint32_t)chunk * 16;
        *(uint4*)(sm + whOff + off) = ((const uint4*)wh)[idx];
        *(uint4*)(sm + wlOff + off) = ((const uint4*)wl)[idx];
    }
}

// ---------------- edge-path per-group (128 threads) A pipeline ----------------
__device__ __forceinline__ void fetch_A32(const float* __restrict__ A, int ge, int M,
                                          float4* v, int gt) {
#pragma unroll
    for (int it = 0; it < 8; ++it) {
        int idx = gt + it * 128;               // 0..1023
        int m = idx >> 5;                      // 0..31
        int k4 = (idx & 31) << 2;
        int gr = ge + m;
        v[it] = (gr < M) ? *(const float4*)(A + (size_t)gr * H + k4)
                         : make_float4(0.f, 0.f, 0.f, 0.f);
    }
}
__device__ __forceinline__ void store_A32(const float4* v, char* sm, int aOff, int gt) {
#pragma unroll
    for (int it = 0; it < 8; ++it) {
        int idx = gt + it * 128;
        int m = idx >> 5;
        int k4 = (idx & 31) << 2;
        uint32_t h0, l0, h1, l1;
        split2(v[it].x, v[it].y, h0, l0);
        split2(v[it].z, v[it].w, h1, l1);
        uint32_t off = (uint32_t)m * ASTRIDE + (uint32_t)k4 * 2;
        *(uint2*)(sm + aOff + off)          = make_uint2(h0, h1);
        *(uint2*)(sm + aOff + E_AG + off)   = make_uint2(l0, l1);
    }
}

// 3-term HMMA, 64-row A tile (node path): warp tile 32x32, wm selects half
__device__ __forceinline__ void gemm_hmma64(uint32_t sb, int wm, int wn, int lane,
                                            float acc[2][4][4]) {
    uint32_t aRowBase = (uint32_t)(wm * 32 + (lane & 15)) * ASTRIDE + (uint32_t)(lane >> 4) * 16;
    uint32_t bRowBase = (uint32_t)(wn * 32 + (lane & 15)) * ASTRIDE + (uint32_t)(lane >> 4) * 16;
#pragma unroll
    for (int t = 0; t < 3; ++t) {
        uint32_t aBase = sb + (t == 2 ? SM_AL : SM_AH) + aRowBase;
        uint32_t wBase = sb + (t == 1 ? SM_WL : SM_WH) + bRowBase;
#pragma unroll
        for (int kf = 0; kf < 8; ++kf) {
            uint32_t af[2][4], bf[2][4];
#pragma unroll
            for (int mf = 0; mf < 2; ++mf)
                ldsm_x4(af[mf], aBase + mf * 16 * ASTRIDE + kf * 32);
#pragma unroll
            for (int p = 0; p < 2; ++p)
                ldsm_x4(bf[p], wBase + p * 16 * ASTRIDE + kf * 32);
#pragma unroll
            for (int mf = 0; mf < 2; ++mf) {
                mma16816(acc[mf][0], af[mf], bf[0][0], bf[0][2]);
                mma16816(acc[mf][1], af[mf], bf[0][1], bf[0][3]);
                mma16816(acc[mf][2], af[mf], bf[1][0], bf[1][2]);
                mma16816(acc[mf][3], af[mf], bf[1][1], bf[1][3]);
            }
        }
    }
}

// 3-term HMMA, 32-row A tile (edge groups): warp tile 32x32
__device__ __forceinline__ void gemm_hmma32(uint32_t sb, uint32_t aOff, int wn, int lane,
                                            float acc[2][4][4]) {
    uint32_t aRowBase = (uint32_t)(lane & 15) * ASTRIDE + (uint32_t)(lane >> 4) * 16;
    uint32_t bRowBase = (uint32_t)(wn * 32 + (lane & 15)) * ASTRIDE + (uint32_t)(lane >> 4) * 16;
#pragma unroll
    for (int t = 0; t < 3; ++t) {
        uint32_t aBase = sb + aOff + (t == 2 ? E_AG : 0) + aRowBase;
        uint32_t wBase = sb + (t == 1 ? E_WL : E_WH) + bRowBase;
#pragma unroll
        for (int kf = 0; kf < 8; ++kf) {
            uint32_t af[2][4], bf[2][4];
#pragma unroll
            for (int mf = 0; mf < 2; ++mf)
                ldsm_x4(af[mf], aBase + mf * 16 * ASTRIDE + kf * 32);
#pragma unroll
            for (int p = 0; p < 2; ++p)
                ldsm_x4(bf[p], wBase + p * 16 * ASTRIDE + kf * 32);
#pragma unroll
            for (int mf = 0; mf < 2; ++mf) {
                mma16816(acc[mf][0], af[mf], bf[0][0], bf[0][2]);
                mma16816(acc[mf][1], af[mf], bf[0][1], bf[0][3]);
                mma16816(acc[mf][2], af[mf], bf[1][0], bf[1][2]);
                mma16816(acc[mf][3], af[mf], bf[1][1], bf[1][3]);
            }
        }
    }
}

// ---------------- launch 0: zero buffers ----------------
__global__ void prep_zero(float* __restrict__ hs, int* __restrict__ cnt, int nh, int nd) {
    int i = blockIdx.x * blockDim.x + threadIdx.x;
    if (i < nh) hs[i] = 0.f;
    if (i < nd) cnt[i] = 0;
}

// ---------------- launch 1: idx convert (per-block dtype sniff) + weight prep ----------------
__device__ __forceinline__ void split_store_w(int t, int n, int k4,
                                              float v0, float v1, float v2, float v3) {
    uint32_t h0, l0, h1, l1;
    split2(v0, v1, h0, l0);
    split2(v2, v3, h1, l1);
    uint32_t off = (uint32_t)n * 256 + (uint32_t)k4 * 2;
    *(uint2*)(g_Wimg + (size_t)t * 32768 + off)       = make_uint2(h0, h1);
    *(uint2*)(g_Wimg + (size_t)(7 + t) * 32768 + off) = make_uint2(l0, l1);
}

__global__ void prep_idx_w(const void* __restrict__ ei, int E, int N, int cBlocks,
                           int* __restrict__ row, int* __restrict__ col,
                           int* __restrict__ cnt,
                           const float* __restrict__ We1, const float* __restrict__ We2,
                           const float* __restrict__ Wn1, const float* __restrict__ Wn2) {
    int tid = threadIdx.x;
    if ((int)blockIdx.x < cBlocks) {
        const long long* p64 = (const long long*)ei;
        long long sv = p64[tid];
        int not64 = __syncthreads_or((sv < 0) | (sv >= (long long)N));
        int e = blockIdx.x * 256 + tid;
        if (e < E) {
            int r, c;
            if (not64) {
                const int* p = (const int*)ei;
                r = p[e]; c = p[E + e];
            } else {
                r = (int)p64[e]; c = (int)p64[(size_t)E + e];
            }
            r = min(max(r, 0), N - 1);
            c = min(max(c, 0), N - 1);
            row[e] = r;
            col[e] = c;
            atomicAdd(&cnt[c], 1);
        }
    } else {
        int task = ((int)blockIdx.x - cBlocks) * 256 + tid;
        if (task >= 7 * 4096) return;
        int t = task >> 12;
        int r = task & 4095;
        int n = r >> 5;
        int k4 = (r & 31) << 2;
        const float* src;
        switch (t) {
            case 0: src = We1;          break;
            case 1: src = We1 + 16384;  break;
            case 2: src = We1 + 32768;  break;
            case 3: src = We2;          break;
            case 4: src = Wn1;          break;
            case 5: src = Wn1 + 16384;  break;
            default: src = Wn2;         break;
        }
        split_store_w(t, n, k4,
                      src[(k4 + 0) * H + n], src[(k4 + 1) * H + n],
                      src[(k4 + 2) * H + n], src[(k4 + 3) * H + n]);
    }
}

// ---------------- launch 2: fused P & Q GEMM ----------------
__global__ void __launch_bounds__(256, 2)
node_pq(const float* __restrict__ x,
        const char* __restrict__ w0h, const char* __restrict__ w0l,
        const char* __restrict__ w1h, const char* __restrict__ w1l,
        const float* __restrict__ be1,
        float* __restrict__ P, float* __restrict__ Q, int M) {
    extern __shared__ char sm[];
    uint32_t sb = smem_u32(sm);
    int tid = threadIdx.x, lane = tid & 31, wid = tid >> 5;
    int wm = wid & 1, wn = wid >> 1;
    int gm = blockIdx.x * BM;
    bool isQ = (blockIdx.y != 0);
    const char* wh = isQ ? w1h : w0h;
    const char* wl = isQ ? w1l : w0l;
    float* C = isQ ? Q : P;

    float acc[2][4][4];
#pragma unroll
    for (int a = 0; a < 2; ++a)
#pragma unroll
        for (int b = 0; b < 4; ++b)
#pragma unroll
            for (int c = 0; c < 4; ++c) acc[a][b][c] = 0.f;

    load_convert_A(x, gm, M, sm, tid);
    copy_W(wh, wl, sm, SM_WH, SM_WL, tid);
    __syncthreads();
    gemm_hmma64(sb, wm, wn, lane, acc);

    int gid = lane >> 2, tig = lane & 3;
#pragma unroll
    for (int mf = 0; mf < 2; ++mf) {
        int r0 = gm + wm * 32 + mf * 16 + gid;
        int r1 = r0 + 8;
#pragma unroll
        for (int nf = 0; nf < 4; ++nf) {
            int c = wn * 32 + nf * 8 + tig * 2;
            float bx = 0.f, by = 0.f;
            if (!isQ) {
                float2 b = *(const float2*)(be1 + c);
                bx = b.x; by = b.y;
            }
            if (r0 < M)
                *(float2*)(C + (size_t)r0 * H + c) =
                    make_float2(acc[mf][nf][0] + bx, acc[mf][nf][1] + by);
            if (r1 < M)
                *(float2*)(C + (size_t)r1 * H + c) =
                    make_float2(acc[mf][nf][2] + bx, acc[mf][nf][3] + by);
        }
    }
}

// ---------------- launch 3: persistent edge GEMM, 2 independent 128-thread groups ----------------
__global__ void __launch_bounds__(256, 2)
edge_gemm(const float* __restrict__ EA, const char* __restrict__ wh, const char* __restrict__ wl,
          const int* __restrict__ rowi, const int* __restrict__ coli,
          const float* __restrict__ P, const float* __restrict__ Q,
          float* __restrict__ Hsum, int E, int nTiles) {
    extern __shared__ char sm[];
    uint32_t sb = smem_u32(sm);
    int tid = threadIdx.x, lane = tid & 31;
    int grp = tid >> 7;                   // 0 or 1
    int gt = tid & 127;                   // tid within group
    int wn = (tid >> 5) & 3;              // warp-in-group
    int barid = 1 + grp;
    int aOff = E_A(grp);
    int* rid = (int*)(sm + E_RID(grp));
    int* cid = (int*)(sm + E_CID(grp));
    int gid = lane >> 2, tig = lane & 3;
    int odd = tig & 1;

    copy_W(wh, wl, sm, E_WH, E_WL, tid);  // whole CTA, once
    __syncthreads();

    int gstride = gridDim.x * 2;
    int t = blockIdx.x * 2 + grp;

    float4 av[8];
    int pr = 0, pc = 0;
    if (t < nTiles) {
        fetch_A32(EA, t * BE, E, av, gt);
        if (gt < 32) {
            int e = t * BE + gt;
            pr = (e < E) ? rowi[e] : 0;
            pc = (e < E) ? coli[e] : 0;
        }
    }

    for (; t < nTiles; t += gstride) {
        int ge = t * BE;
        int tn = t + gstride;

        store_A32(av, sm, aOff, gt);
        if (gt < 32) { rid[gt] = pr; cid[gt] = pc; }
        BAR_G(barid);

        float acc[2][4][4];
#pragma unroll
        for (int a = 0; a < 2; ++a)
#pragma unroll
            for (int b = 0; b < 4; ++b)
#pragma unroll
                for (int c = 0; c < 4; ++c) acc[a][b][c] = 0.f;
        gemm_hmma32(sb, aOff, wn, lane, acc);

        // prefetch next tile (overlaps epilogue)
        if (tn < nTiles) {
            fetch_A32(EA, tn * BE, E, av, gt);
            if (gt < 32) {
                int e = tn * BE + gt;
                pr = (e < E) ? rowi[e] : 0;
                pc = (e < E) ? coli[e] : 0;
            }
        }

        // epilogue: shfl-pair into float4 rows; gather P/Q; relu; red.v4
#pragma unroll
        for (int mf = 0; mf < 2; ++mf) {
            int rl = mf * 16 + gid + (odd << 3);     // 0..31
            int e = ge + rl;
            int r = rid[rl], c = cid[rl];
            bool ok = (e < E);
#pragma unroll
            for (int nf = 0; nf < 4; ++nf) {
                float sA = odd ? acc[mf][nf][0] : acc[mf][nf][2];
                float sB = odd ? acc[mf][nf][1] : acc[mf][nf][3];
                float rA = __shfl_xor_sync(0xffffffffu, sA, 1);
                float rB = __shfl_xor_sync(0xffffffffu, sB, 1);
                float4 v;
                if (odd) v = make_float4(rA, rB, acc[mf][nf][2], acc[mf][nf][3]);
                else     v = make_float4(acc[mf][nf][0], acc[mf][nf][1], rA, rB);
                int cb = wn * 32 + nf * 8 + (tig & 2) * 2;
                if (ok) {
                    float4 pv = *(const float4*)(P + (size_t)r * H + cb);
                    float4 qv = *(const float4*)(Q + (size_t)c * H + cb);
                    v.x = fmaxf(v.x + pv.x + qv.x, 0.f);
                    v.y = fmaxf(v.y + pv.y + qv.y, 0.f);
                    v.z = fmaxf(v.z + pv.z + qv.z, 0.f);
                    v.w = fmaxf(v.w + pv.w + qv.w, 0.f);
                    red_add_v4(Hsum + (size_t)c * H + cb, v);
                }
            }
        }
        BAR_G(barid);   // group done reading A/ids before next overwrite
    }
}

// ---------------- launches 4-6: node GEMMs ----------------
template<bool DUAL, bool RELU, int BIAS_MODE>
__global__ void __launch_bounds__(256, 2)
node_gemm(const float* __restrict__ A1, const char* __restrict__ w1h, const char* __restrict__ w1l,
          const float* __restrict__ A2, const char* __restrict__ w2h, const char* __restrict__ w2l,
          const float* __restrict__ bias, const int* __restrict__ cnt,
          float* __restrict__ C, int M) {
    extern __shared__ char sm[];
    uint32_t sb = smem_u32(sm);
    int tid = threadIdx.x, lane = tid & 31, wid = tid >> 5;
    int wm = wid & 1, wn = wid >> 1;
    int gm = blockIdx.x * BM;

    float acc[2][4][4];
#pragma unroll
    for (int a = 0; a < 2; ++a)
#pragma unroll
        for (int b = 0; b < 4; ++b)
#pragma unroll
            for (int c = 0; c < 4; ++c) acc[a][b][c] = 0.f;

    load_convert_A(A1, gm, M, sm, tid);
    copy_W(w1h, w1l, sm, SM_WH, SM_WL, tid);
    __syncthreads();
    gemm_hmma64(sb, wm, wn, lane, acc);
    if (DUAL) {
        __syncthreads();
        load_convert_A(A2, gm, M, sm, tid);
        copy_W(w2h, w2l, sm, SM_WH, SM_WL, tid);
        __syncthreads();
        gemm_hmma64(sb, wm, wn, lane, acc);
    }

    int gid = lane >> 2, tig = lane & 3;
#pragma unroll
    for (int mf = 0; mf < 2; ++mf) {
        int r0 = gm + wm * 32 + mf * 16 + gid;
        int r1 = r0 + 8;
        float d0 = 0.f, d1 = 0.f;
        if (BIAS_MODE == 2) {
            if (r0 < M) d0 = (float)cnt[r0];
            if (r1 < M) d1 = (float)cnt[r1];
        }
#pragma unroll
        for (int nf = 0; nf < 4; ++nf) {
            int c = wn * 32 + nf * 8 + tig * 2;
            float bx = 0.f, by = 0.f;
            if (BIAS_MODE != 0) {
                float2 b = *(const float2*)(bias + c);
                bx = b.x; by = b.y;
            }
            if (r0 < M) {
                float vx = acc[mf][nf][0], vy = acc[mf][nf][1];
                if (BIAS_MODE == 1) { vx += bx; vy += by; }
                else if (BIAS_MODE == 2) { vx += d0 * bx; vy += d0 * by; }
                if (RELU) { vx = fmaxf(vx, 0.f); vy = fmaxf(vy, 0.f); }
                *(float2*)(C + (size_t)r0 * H + c) = make_float2(vx, vy);
            }
            if (r1 < M) {
                float vx = acc[mf][nf][2], vy = acc[mf][nf][3];
                if (BIAS_MODE == 1) { vx += bx; vy += by; }
                else if (BIAS_MODE == 2) { vx += d1 * bx; vy += d1 * by; }
                if (RELU) { vx = fmaxf(vx, 0.f); vy = fmaxf(vy, 0.f); }
                *(float2*)(C + (size_t)r1 * H + c) = make_float2(vx, vy);
            }
        }
    }
}

// ---------------- host ----------------
extern "C" void kernel_launch(void* const* d_in, const int* in_sizes, int n_in,
                              void* d_out, int out_size) {
    const float* x   = (const float*)d_in[0];
    const void*  ei  = d_in[1];
    const float* ea  = (const float*)d_in[2];
    const float* We1 = (const float*)d_in[3];
    const float* be1 = (const float*)d_in[4];
    const float* We2 = (const float*)d_in[5];
    const float* be2 = (const float*)d_in[6];
    const float* Wn1 = (const float*)d_in[7];
    const float* bn1 = (const float*)d_in[8];
    const float* Wn2 = (const float*)d_in[9];
    const float* bn2 = (const float*)d_in[10];
    float* out = (float*)d_out;

    int N = in_sizes[0] / H;
    int E = in_sizes[1] / 2;

    void *pP, *pQ, *pHs, *pAgg, *pT, *pCnt, *pRow, *pCol, *pWimg;
    cudaGetSymbolAddress(&pP, g_P);
    cudaGetSymbolAddress(&pQ, g_Q);
    cudaGetSymbolAddress(&pHs, g_Hsum);
    cudaGetSymbolAddress(&pAgg, g_agg);
    cudaGetSymbolAddress(&pT, g_Tbuf);
    cudaGetSymbolAddress(&pCnt, g_cnt);
    cudaGetSymbolAddress(&pRow, g_row);
    cudaGetSymbolAddress(&pCol, g_col);
    cudaGetSymbolAddress(&pWimg, g_Wimg);
    float* P   = (float*)pP;
    float* Q   = (float*)pQ;
    float* Hs  = (float*)pHs;
    float* agg = (float*)pAgg;
    float* T   = (float*)pT;
    int*   cnt = (int*)pCnt;
    int*   ro  = (int*)pRow;
    int*   co  = (int*)pCol;
    const char* W = (const char*)pWimg;
    auto wH = [&](int t) { return W + (size_t)t * 32768; };
    auto wL = [&](int t) { return W + (size_t)(7 + t) * 32768; };

    cudaFuncSetAttribute(node_pq, cudaFuncAttributeMaxDynamicSharedMemorySize, SMEM_NODE);
    cudaFuncSetAttribute(edge_gemm, cudaFuncAttributeMaxDynamicSharedMemorySize, SMEM_EDGE);
    cudaFuncSetAttribute(node_gemm<false, false, 1>, cudaFuncAttributeMaxDynamicSharedMemorySize, SMEM_NODE);
    cudaFuncSetAttribute(node_gemm<false, false, 2>, cudaFuncAttributeMaxDynamicSharedMemorySize, SMEM_NODE);
    cudaFuncSetAttribute(node_gemm<true,  true,  1>, cudaFuncAttributeMaxDynamicSharedMemorySize, SMEM_NODE);

    int nodeBlocks = (N + BM - 1) / BM;              // 782
    int nTiles = (E + BE - 1) / BE;                  // 25000
    int nh = N * H;
    int cBlocks = (E + 255) / 256;                   // 3125
    int persistCTAs = 148 * 2;

    prep_zero<<<(nh + 255) / 256, 256>>>(Hs, cnt, nh, N);
    prep_idx_w<<<cBlocks + 112, 256>>>(ei, E, N, cBlocks, ro, co, cnt, We1, We2, Wn1, Wn2);
    node_pq<<<dim3(nodeBlocks, 2), 256, SMEM_NODE>>>(x, wH(0), wL(0), wH(1), wL(1), be1, P, Q, N);
    edge_gemm<<<persistCTAs, 256, SMEM_EDGE>>>(ea, wH(2), wL(2), ro, co, P, Q, Hs, E, nTiles);
    node_gemm<false, false, 2><<<nodeBlocks, 256, SMEM_NODE>>>(Hs, wH(3), wL(3), nullptr, nullptr, nullptr, be2, cnt, agg, N);
    node_gemm<true, true, 1><<<nodeBlocks, 256, SMEM_NODE>>>(x, wH(4), wL(4), agg, wH(5), wL(5), bn1, nullptr, T, N);
    node_gemm<false, false, 1><<<nodeBlocks, 256, SMEM_NODE>>>(T, wH(6), wL(6), nullptr, nullptr, nullptr, bn2, nullptr, out, N);
}

// round 14
// speedup vs baseline: 1.1353x; 1.1353x over previous
#include <cuda_runtime.h>
#include <cuda_bf16.h>
#include <cstdint>

#define H 128
#define BM 64
#define MAXN 50176
#define MAXE 800000

// ---------------- scratch (device globals) ----------------
__device__ float g_P[MAXN * H];
__device__ float g_Q[MAXN * H];
__device__ float g_Hsum[MAXN * H];
__device__ float g_agg[MAXN * H];
__device__ float g_Tbuf[MAXN * H];
__device__ float g_R[MAXE * H];      // edge GEMM result (409.6 MB)
__device__ int   g_cnt[MAXN];
__device__ int   g_row[MAXE];
__device__ int   g_col[MAXE];
__device__ __align__(16) char g_Wimg[14 * 32768];

// ---------------- smem layout (shared by node + edge GEMM kernels) ----------------
#define ASTRIDE 272
#define ATILE   (64 * ASTRIDE)           // 17408
#define WTILE   (128 * ASTRIDE)          // 34816
#define SM_AH   0
#define SM_AL   ATILE
#define SM_WH   (2 * ATILE)
#define SM_WL   (2 * ATILE + WTILE)
#define SMEM_GEMM (2 * ATILE + 2 * WTILE)        // 104448

// ---------------- PTX helpers ----------------
__device__ __forceinline__ uint32_t smem_u32(const void* p) {
    uint32_t a;
    asm("{ .reg .u64 t; cvta.to.shared.u64 t, %1; cvt.u32.u64 %0, t; }" : "=r"(a) : "l"(p));
    return a;
}
__device__ __forceinline__ void ldsm_x4(uint32_t* r, uint32_t addr) {
    asm volatile("ldmatrix.sync.aligned.m8n8.x4.shared.b16 {%0,%1,%2,%3}, [%4];"
                 : "=r"(r[0]), "=r"(r[1]), "=r"(r[2]), "=r"(r[3]) : "r"(addr));
}
__device__ __forceinline__ void mma16816(float* d, const uint32_t* a, uint32_t b0, uint32_t b1) {
    asm volatile("mma.sync.aligned.m16n8k16.row.col.f32.bf16.bf16.f32 "
                 "{%0,%1,%2,%3}, {%4,%5,%6,%7}, {%8,%9}, {%0,%1,%2,%3};"
                 : "+f"(d[0]), "+f"(d[1]), "+f"(d[2]), "+f"(d[3])
                 : "r"(a[0]), "r"(a[1]), "r"(a[2]), "r"(a[3]), "r"(b0), "r"(b1));
}
__device__ __forceinline__ void red_add_v4(float* p, float4 v) {
    asm volatile("red.global.add.v4.f32 [%0], {%1,%2,%3,%4};"
                 :: "l"(p), "f"(v.x), "f"(v.y), "f"(v.z), "f"(v.w) : "memory");
}

__device__ __forceinline__ void split2(float a, float b, uint32_t& hi, uint32_t& lo) {
    __nv_bfloat16 ha = __float2bfloat16_rn(a), hb = __float2bfloat16_rn(b);
    float ra = a - __bfloat162float(ha), rb = b - __bfloat162float(hb);
    __nv_bfloat16 la = __float2bfloat16_rn(ra), lb = __float2bfloat16_rn(rb);
    hi = ((uint32_t)*(uint16_t*)&hb << 16) | (uint32_t)*(uint16_t*)&ha;
    lo = ((uint32_t)*(uint16_t*)&lb << 16) | (uint32_t)*(uint16_t*)&la;
}

// ---------------- A/W loaders (256 threads) ----------------
__device__ __forceinline__ void load_convert_A(const float* __restrict__ A, int gm, int M,
                                               char* sm, int tid) {
#pragma unroll
    for (int it = 0; it < 8; ++it) {
        int idx = tid + it * 256;
        int m = idx >> 5;
        int k4 = (idx & 31) << 2;
        float4 v = make_float4(0.f, 0.f, 0.f, 0.f);
        int gr = gm + m;
        if (gr < M) v = *(const float4*)(A + (size_t)gr * H + k4);
        uint32_t h0, l0, h1, l1;
        split2(v.x, v.y, h0, l0);
        split2(v.z, v.w, h1, l1);
        uint32_t off = (uint32_t)m * ASTRIDE + (uint32_t)k4 * 2;
        *(uint2*)(sm + SM_AH + off) = make_uint2(h0, h1);
        *(uint2*)(sm + SM_AL + off) = make_uint2(l0, l1);
    }
}
__device__ __forceinline__ void fetch_A(const float* __restrict__ A, int gm, int M,
                                        float4* v, int tid) {
#pragma unroll
    for (int it = 0; it < 8; ++it) {
        int idx = tid + it * 256;
        int m = idx >> 5;
        int k4 = (idx & 31) << 2;
        int gr = gm + m;
        v[it] = (gr < M) ? *(const float4*)(A + (size_t)gr * H + k4)
                         : make_float4(0.f, 0.f, 0.f, 0.f);
    }
}
__device__ __forceinline__ void store_A(const float4* v, char* sm, int tid) {
#pragma unroll
    for (int it = 0; it < 8; ++it) {
        int idx = tid + it * 256;
        int m = idx >> 5;
        int k4 = (idx & 31) << 2;
        uint32_t h0, l0, h1, l1;
        split2(v[it].x, v[it].y, h0, l0);
        split2(v[it].z, v[it].w, h1, l1);
        uint32_t off = (uint32_t)m * ASTRIDE + (uint32_t)k4 * 2;
        *(uint2*)(sm + SM_AH + off) = make_uint2(h0, h1);
        *(uint2*)(sm + SM_AL + off) = make_uint2(l0, l1);
    }
}
__device__ __forceinline__ void copy_W(const char* __restrict__ wh, const char* __restrict__ wl,
                                       char* sm, int tid) {
#pragma unroll
    for (int it = 0; it < 8; ++it) {
        int idx = tid + it * 256;
        int row = idx >> 4;
        int chunk = idx & 15;
        uint32_t off = (uint32_t)row * ASTRIDE + (uint32_t)chunk * 16;
        *(uint4*)(sm + SM_WH + off) = ((const uint4*)wh)[idx];
        *(uint4*)(sm + SM_WL + off) = ((const uint4*)wl)[idx];
    }
}

// 3-term compensated HMMA: acc += Ah*Wh + Ah*Wl + Al*Wh   (warp tile 32x32)
__device__ __forceinline__ void gemm_hmma(uint32_t sb, int wm, int wn, int lane,
                                          float acc[2][4][4]) {
    uint32_t aRowBase = (uint32_t)(wm * 32 + (lane & 15)) * ASTRIDE + (uint32_t)(lane >> 4) * 16;
    uint32_t bRowBase = (uint32_t)(wn * 32 + (lane & 15)) * ASTRIDE + (uint32_t)(lane >> 4) * 16;
#pragma unroll
    for (int t = 0; t < 3; ++t) {
        uint32_t aBase = sb + (t == 2 ? SM_AL : SM_AH) + aRowBase;
        uint32_t wBase = sb + (t == 1 ? SM_WL : SM_WH) + bRowBase;
#pragma unroll
        for (int kf = 0; kf < 8; ++kf) {
            uint32_t af[2][4], bf[2][4];
#pragma unroll
            for (int mf = 0; mf < 2; ++mf)
                ldsm_x4(af[mf], aBase + mf * 16 * ASTRIDE + kf * 32);
#pragma unroll
            for (int p = 0; p < 2; ++p)
                ldsm_x4(bf[p], wBase + p * 16 * ASTRIDE + kf * 32);
#pragma unroll
            for (int mf = 0; mf < 2; ++mf) {
                mma16816(acc[mf][0], af[mf], bf[0][0], bf[0][2]);
                mma16816(acc[mf][1], af[mf], bf[0][1], bf[0][3]);
                mma16816(acc[mf][2], af[mf], bf[1][0], bf[1][2]);
                mma16816(acc[mf][3], af[mf], bf[1][1], bf[1][3]);
            }
        }
    }
}

// ---------------- launch 0: zero buffers ----------------
__global__ void prep_zero(float* __restrict__ hs, int* __restrict__ cnt, int nh, int nd) {
    int i = blockIdx.x * blockDim.x + threadIdx.x;
    if (i < nh) hs[i] = 0.f;
    if (i < nd) cnt[i] = 0;
}

// ---------------- launch 1: idx convert (per-block dtype sniff) + weight prep ----------------
__device__ __forceinline__ void split_store_w(int t, int n, int k4,
                                              float v0, float v1, float v2, float v3) {
    uint32_t h0, l0, h1, l1;
    split2(v0, v1, h0, l0);
    split2(v2, v3, h1, l1);
    uint32_t off = (uint32_t)n * 256 + (uint32_t)k4 * 2;
    *(uint2*)(g_Wimg + (size_t)t * 32768 + off)       = make_uint2(h0, h1);
    *(uint2*)(g_Wimg + (size_t)(7 + t) * 32768 + off) = make_uint2(l0, l1);
}

__global__ void prep_idx_w(const void* __restrict__ ei, int E, int N, int cBlocks,
                           int* __restrict__ row, int* __restrict__ col,
                           int* __restrict__ cnt,
                           const float* __restrict__ We1, const float* __restrict__ We2,
                           const float* __restrict__ Wn1, const float* __restrict__ Wn2) {
    int tid = threadIdx.x;
    if ((int)blockIdx.x < cBlocks) {
        const long long* p64 = (const long long*)ei;
        long long sv = p64[tid];
        int not64 = __syncthreads_or((sv < 0) | (sv >= (long long)N));
        int e = blockIdx.x * 256 + tid;
        if (e < E) {
            int r, c;
            if (not64) {
                const int* p = (const int*)ei;
                r = p[e]; c = p[E + e];
            } else {
                r = (int)p64[e]; c = (int)p64[(size_t)E + e];
            }
            r = min(max(r, 0), N - 1);
            c = min(max(c, 0), N - 1);
            row[e] = r;
            col[e] = c;
            atomicAdd(&cnt[c], 1);
        }
    } else {
        int task = ((int)blockIdx.x - cBlocks) * 256 + tid;
        if (task >= 7 * 4096) return;
        int t = task >> 12;
        int r = task & 4095;
        int n = r >> 5;
        int k4 = (r & 31) << 2;
        const float* src;
        switch (t) {
            case 0: src = We1;          break;
            case 1: src = We1 + 16384;  break;
            case 2: src = We1 + 32768;  break;
            case 3: src = We2;          break;
            case 4: src = Wn1;          break;
            case 5: src = Wn1 + 16384;  break;
            default: src = Wn2;         break;
        }
        split_store_w(t, n, k4,
                      src[(k4 + 0) * H + n], src[(k4 + 1) * H + n],
                      src[(k4 + 2) * H + n], src[(k4 + 3) * H + n]);
    }
}

// ---------------- launch 2: fused P & Q GEMM ----------------
__global__ void __launch_bounds__(256, 2)
node_pq(const float* __restrict__ x,
        const char* __restrict__ w0h, const char* __restrict__ w0l,
        const char* __restrict__ w1h, const char* __restrict__ w1l,
        const float* __restrict__ be1,
        float* __restrict__ P, float* __restrict__ Q, int M) {
    extern __shared__ char sm[];
    uint32_t sb = smem_u32(sm);
    int tid = threadIdx.x, lane = tid & 31, wid = tid >> 5;
    int wm = wid & 1, wn = wid >> 1;
    int gm = blockIdx.x * BM;
    bool isQ = (blockIdx.y != 0);
    const char* wh = isQ ? w1h : w0h;
    const char* wl = isQ ? w1l : w0l;
    float* C = isQ ? Q : P;

    float acc[2][4][4];
#pragma unroll
    for (int a = 0; a < 2; ++a)
#pragma unroll
        for (int b = 0; b < 4; ++b)
#pragma unroll
            for (int c = 0; c < 4; ++c) acc[a][b][c] = 0.f;

    load_convert_A(x, gm, M, sm, tid);
    copy_W(wh, wl, sm, tid);
    __syncthreads();
    gemm_hmma(sb, wm, wn, lane, acc);

    int gid = lane >> 2, tig = lane & 3;
#pragma unroll
    for (int mf = 0; mf < 2; ++mf) {
        int r0 = gm + wm * 32 + mf * 16 + gid;
        int r1 = r0 + 8;
#pragma unroll
        for (int nf = 0; nf < 4; ++nf) {
            int c = wn * 32 + nf * 8 + tig * 2;
            float bx = 0.f, by = 0.f;
            if (!isQ) {
                float2 b = *(const float2*)(be1 + c);
                bx = b.x; by = b.y;
            }
            if (r0 < M)
                *(float2*)(C + (size_t)r0 * H + c) =
                    make_float2(acc[mf][nf][0] + bx, acc[mf][nf][1] + by);
            if (r1 < M)
                *(float2*)(C + (size_t)r1 * H + c) =
                    make_float2(acc[mf][nf][2] + bx, acc[mf][nf][3] + by);
        }
    }
}

// ---------------- launch 3: persistent edge GEMM -> R (no gathers, no reds) ----------------
__global__ void __launch_bounds__(256, 2)
edge_gemm(const float* __restrict__ EA, const char* __restrict__ wh, const char* __restrict__ wl,
          float* __restrict__ Rg, int E, int nTiles) {
    extern __shared__ char sm[];
    uint32_t sb = smem_u32(sm);
    int tid = threadIdx.x, lane = tid & 31, wid = tid >> 5;
    int wm = wid & 1, wn = wid >> 1;
    int gid = lane >> 2, tig = lane & 3;

    copy_W(wh, wl, sm, tid);                 // once per CTA

    int t = blockIdx.x;
    float4 av[8];
    if (t < nTiles) fetch_A(EA, t * BM, E, av, tid);

    for (; t < nTiles; t += gridDim.x) {
        int ge = t * BM;
        int tn = t + gridDim.x;

        store_A(av, sm, tid);
        __syncthreads();

        float acc[2][4][4];
#pragma unroll
        for (int a = 0; a < 2; ++a)
#pragma unroll
            for (int b = 0; b < 4; ++b)
#pragma unroll
                for (int c = 0; c < 4; ++c) acc[a][b][c] = 0.f;
        gemm_hmma(sb, wm, wn, lane, acc);

        if (tn < nTiles) fetch_A(EA, tn * BM, E, av, tid);   // overlaps epilogue

        // epilogue: coalesced stores of raw GEMM result
#pragma unroll
        for (int mf = 0; mf < 2; ++mf) {
            int r0 = ge + wm * 32 + mf * 16 + gid;
            int r1 = r0 + 8;
#pragma unroll
            for (int nf = 0; nf < 4; ++nf) {
                int c = wn * 32 + nf * 8 + tig * 2;
                if (r0 < E)
                    *(float2*)(Rg + (size_t)r0 * H + c) = make_float2(acc[mf][nf][0], acc[mf][nf][1]);
                if (r1 < E)
                    *(float2*)(Rg + (size_t)r1 * H + c) = make_float2(acc[mf][nf][2], acc[mf][nf][3]);
            }
        }
        __syncthreads();
    }
}

// ---------------- launch 4: edge scatter (full occupancy, one warp per edge) ----------------
__global__ void __launch_bounds__(256)
edge_scatter(const float* __restrict__ Rg,
             const int* __restrict__ rowi, const int* __restrict__ coli,
             const float* __restrict__ P, const float* __restrict__ Q,
             float* __restrict__ Hsum, int E) {
    int e = (blockIdx.x * 256 + threadIdx.x) >> 5;
    int lane = threadIdx.x & 31;
    if (e >= E) return;
    int r = rowi[e], c = coli[e];        // uniform within warp -> L1 broadcast
    int cb = lane * 4;
    float4 rv = *(const float4*)(Rg + (size_t)e * H + cb);
    float4 pv = *(const float4*)(P + (size_t)r * H + cb);
    float4 qv = *(const float4*)(Q + (size_t)c * H + cb);
    float4 v;
    v.x = fmaxf(rv.x + pv.x + qv.x, 0.f);
    v.y = fmaxf(rv.y + pv.y + qv.y, 0.f);
    v.z = fmaxf(rv.z + pv.z + qv.z, 0.f);
    v.w = fmaxf(rv.w + pv.w + qv.w, 0.f);
    red_add_v4(Hsum + (size_t)c * H + cb, v);
}

// ---------------- launches 5-7: node GEMMs ----------------
template<bool DUAL, bool RELU, int BIAS_MODE>
__global__ void __launch_bounds__(256, 2)
node_gemm(const float* __restrict__ A1, const char* __restrict__ w1h, const char* __restrict__ w1l,
          const float* __restrict__ A2, const char* __restrict__ w2h, const char* __restrict__ w2l,
          const float* __restrict__ bias, const int* __restrict__ cnt,
          float* __restrict__ C, int M) {
    extern __shared__ char sm[];
    uint32_t sb = smem_u32(sm);
    int tid = threadIdx.x, lane = tid & 31, wid = tid >> 5;
    int wm = wid & 1, wn = wid >> 1;
    int gm = blockIdx.x * BM;

    float acc[2][4][4];
#pragma unroll
    for (int a = 0; a < 2; ++a)
#pragma unroll
        for (int b = 0; b < 4; ++b)
#pragma unroll
            for (int c = 0; c < 4; ++c) acc[a][b][c] = 0.f;

    load_convert_A(A1, gm, M, sm, tid);
    copy_W(w1h, w1l, sm, tid);
    __syncthreads();
    gemm_hmma(sb, wm, wn, lane, acc);
    if (DUAL) {
        __syncthreads();
        load_convert_A(A2, gm, M, sm, tid);
        copy_W(w2h, w2l, sm, tid);
        __syncthreads();
        gemm_hmma(sb, wm, wn, lane, acc);
    }

    int gid = lane >> 2, tig = lane & 3;
#pragma unroll
    for (int mf = 0; mf < 2; ++mf) {
        int r0 = gm + wm * 32 + mf * 16 + gid;
        int r1 = r0 + 8;
        float d0 = 0.f, d1 = 0.f;
        if (BIAS_MODE == 2) {
            if (r0 < M) d0 = (float)cnt[r0];
            if (r1 < M) d1 = (float)cnt[r1];
        }
#pragma unroll
        for (int nf = 0; nf < 4; ++nf) {
            int c = wn * 32 + nf * 8 + tig * 2;
            float bx = 0.f, by = 0.f;
            if (BIAS_MODE != 0) {
                float2 b = *(const float2*)(bias + c);
                bx = b.x; by = b.y;
            }
            if (r0 < M) {
                float vx = acc[mf][nf][0], vy = acc[mf][nf][1];
                if (BIAS_MODE == 1) { vx += bx; vy += by; }
                else if (BIAS_MODE == 2) { vx += d0 * bx; vy += d0 * by; }
                if (RELU) { vx = fmaxf(vx, 0.f); vy = fmaxf(vy, 0.f); }
                *(float2*)(C + (size_t)r0 * H + c) = make_float2(vx, vy);
            }
            if (r1 < M) {
                float vx = acc[mf][nf][2], vy = acc[mf][nf][3];
                if (BIAS_MODE == 1) { vx += bx; vy += by; }
                else if (BIAS_MODE == 2) { vx += d1 * bx; vy += d1 * by; }
                if (RELU) { vx = fmaxf(vx, 0.f); vy = fmaxf(vy, 0.f); }
                *(float2*)(C + (size_t)r1 * H + c) = make_float2(vx, vy);
            }
        }
    }
}

// ---------------- host ----------------
extern "C" void kernel_launch(void* const* d_in, const int* in_sizes, int n_in,
                              void* d_out, int out_size) {
    const float* x   = (const float*)d_in[0];
    const void*  ei  = d_in[1];
    const float* ea  = (const float*)d_in[2];
    const float* We1 = (const float*)d_in[3];
    const float* be1 = (const float*)d_in[4];
    const float* We2 = (const float*)d_in[5];
    const float* be2 = (const float*)d_in[6];
    const float* Wn1 = (const float*)d_in[7];
    const float* bn1 = (const float*)d_in[8];
    const float* Wn2 = (const float*)d_in[9];
    const float* bn2 = (const float*)d_in[10];
    float* out = (float*)d_out;

    int N = in_sizes[0] / H;
    int E = in_sizes[1] / 2;

    void *pP, *pQ, *pHs, *pAgg, *pT, *pR, *pCnt, *pRow, *pCol, *pWimg;
    cudaGetSymbolAddress(&pP, g_P);
    cudaGetSymbolAddress(&pQ, g_Q);
    cudaGetSymbolAddress(&pHs, g_Hsum);
    cudaGetSymbolAddress(&pAgg, g_agg);
    cudaGetSymbolAddress(&pT, g_Tbuf);
    cudaGetSymbolAddress(&pR, g_R);
    cudaGetSymbolAddress(&pCnt, g_cnt);
    cudaGetSymbolAddress(&pRow, g_row);
    cudaGetSymbolAddress(&pCol, g_col);
    cudaGetSymbolAddress(&pWimg, g_Wimg);
    float* P   = (float*)pP;
    float* Q   = (float*)pQ;
    float* Hs  = (float*)pHs;
    float* agg = (float*)pAgg;
    float* T   = (float*)pT;
    float* Rg  = (float*)pR;
    int*   cnt = (int*)pCnt;
    int*   ro  = (int*)pRow;
    int*   co  = (int*)pCol;
    const char* W = (const char*)pWimg;
    auto wH = [&](int t) { return W + (size_t)t * 32768; };
    auto wL = [&](int t) { return W + (size_t)(7 + t) * 32768; };

    cudaFuncSetAttribute(node_pq, cudaFuncAttributeMaxDynamicSharedMemorySize, SMEM_GEMM);
    cudaFuncSetAttribute(edge_gemm, cudaFuncAttributeMaxDynamicSharedMemorySize, SMEM_GEMM);
    cudaFuncSetAttribute(node_gemm<false, false, 1>, cudaFuncAttributeMaxDynamicSharedMemorySize, SMEM_GEMM);
    cudaFuncSetAttribute(node_gemm<false, false, 2>, cudaFuncAttributeMaxDynamicSharedMemorySize, SMEM_GEMM);
    cudaFuncSetAttribute(node_gemm<true,  true,  1>, cudaFuncAttributeMaxDynamicSharedMemorySize, SMEM_GEMM);

    int nodeBlocks = (N + BM - 1) / BM;              // 784
    int nTiles = (E + BM - 1) / BM;                  // 12500
    int nh = N * H;
    int cBlocks = (E + 255) / 256;                   // 3125
    int persistCTAs = 148 * 2;
    int scatBlocks = (E * 32 + 255) / 256;           // 100000

    // launch 0: zero Hsum + cnt
    prep_zero<<<(nh + 255) / 256, 256>>>(Hs, cnt, nh, N);
    // launch 1: idx convert (per-block dtype sniff) + weight images
    prep_idx_w<<<cBlocks + 112, 256>>>(ei, E, N, cBlocks, ro, co, cnt, We1, We2, Wn1, Wn2);
    // launch 2: P = x@We1a + be1  AND  Q = x@We1b
    node_pq<<<dim3(nodeBlocks, 2), 256, SMEM_GEMM>>>(x, wH(0), wL(0), wH(1), wL(1), be1, P, Q, N);
    // launch 3 (ncu capture slot): pure edge GEMM -> R
    edge_gemm<<<persistCTAs, 256, SMEM_GEMM>>>(ea, wH(2), wL(2), Rg, E, nTiles);
    // launch 4: scatter h = relu(R + P[row] + Q[col]) into Hsum (full occupancy)
    edge_scatter<<<scatBlocks, 256>>>(Rg, ro, co, P, Q, Hs, E);
    // launch 5: agg = Hsum@We2 + deg*be2
    node_gemm<false, false, 2><<<nodeBlocks, 256, SMEM_GEMM>>>(Hs, wH(3), wL(3), nullptr, nullptr, nullptr, be2, cnt, agg, N);
    // launch 6: T = relu(x@Wn1a + agg@Wn1b + bn1)
    node_gemm<true, true, 1><<<nodeBlocks, 256, SMEM_GEMM>>>(x, wH(4), wL(4), agg, wH(5), wL(5), bn1, nullptr, T, N);
    // launch 7: out = T@Wn2 + bn2
    node_gemm<false, false, 1><<<nodeBlocks, 256, SMEM_GEMM>>>(T, wH(6), wL(6), nullptr, nullptr, nullptr, bn2, nullptr, out, N);
}

// round 15
// speedup vs baseline: 1.3937x; 1.2276x over previous
#include <cuda_runtime.h>
#include <cuda_bf16.h>
#include <cstdint>

#define H 128
#define BM 64
#define MAXN 50176
#define MAXE 800000

// ---------------- scratch (device globals) ----------------
__device__ float g_P[MAXN * H];
__device__ float g_Q[MAXN * H];
__device__ float g_Hsum[MAXN * H];
__device__ float g_agg[MAXN * H];
__device__ float g_Tbuf[MAXN * H];
__device__ float g_R[MAXE * H];      // edge GEMM result
__device__ int   g_cnt[MAXN];
__device__ int   g_row[MAXE];
__device__ int   g_col[MAXE];
__device__ __align__(16) char g_Wimg[14 * 32768];

// ---------------- smem layout ----------------
#define ASTRIDE 272
#define ATILE   (64 * ASTRIDE)           // 17408
#define WTILE   (128 * ASTRIDE)          // 34816
#define SM_AH   0
#define SM_AL   ATILE
#define SM_WH   (2 * ATILE)
#define SM_WL   (2 * ATILE + WTILE)
#define SMEM_GEMM (2 * ATILE + 2 * WTILE)        // 104448

// ---------------- PTX helpers ----------------
__device__ __forceinline__ uint32_t smem_u32(const void* p) {
    uint32_t a;
    asm("{ .reg .u64 t; cvta.to.shared.u64 t, %1; cvt.u32.u64 %0, t; }" : "=r"(a) : "l"(p));
    return a;
}
__device__ __forceinline__ void ldsm_x4(uint32_t* r, uint32_t addr) {
    asm volatile("ldmatrix.sync.aligned.m8n8.x4.shared.b16 {%0,%1,%2,%3}, [%4];"
                 : "=r"(r[0]), "=r"(r[1]), "=r"(r[2]), "=r"(r[3]) : "r"(addr));
}
__device__ __forceinline__ void mma16816(float* d, const uint32_t* a, uint32_t b0, uint32_t b1) {
    asm volatile("mma.sync.aligned.m16n8k16.row.col.f32.bf16.bf16.f32 "
                 "{%0,%1,%2,%3}, {%4,%5,%6,%7}, {%8,%9}, {%0,%1,%2,%3};"
                 : "+f"(d[0]), "+f"(d[1]), "+f"(d[2]), "+f"(d[3])
                 : "r"(a[0]), "r"(a[1]), "r"(a[2]), "r"(a[3]), "r"(b0), "r"(b1));
}
__device__ __forceinline__ void red_add_v4(float* p, float4 v) {
    asm volatile("red.global.add.v4.f32 [%0], {%1,%2,%3,%4};"
                 :: "l"(p), "f"(v.x), "f"(v.y), "f"(v.z), "f"(v.w) : "memory");
}

__device__ __forceinline__ void split2(float a, float b, uint32_t& hi, uint32_t& lo) {
    __nv_bfloat16 ha = __float2bfloat16_rn(a), hb = __float2bfloat16_rn(b);
    float ra = a - __bfloat162float(ha), rb = b - __bfloat162float(hb);
    __nv_bfloat16 la = __float2bfloat16_rn(ra), lb = __float2bfloat16_rn(rb);
    hi = ((uint32_t)*(uint16_t*)&hb << 16) | (uint32_t)*(uint16_t*)&ha;
    lo = ((uint32_t)*(uint16_t*)&lb << 16) | (uint32_t)*(uint16_t*)&la;
}

// ---------------- A/W loaders (256 threads) ----------------
__device__ __forceinline__ void load_convert_A(const float* __restrict__ A, int gm, int M,
                                               char* sm, int tid) {
#pragma unroll
    for (int it = 0; it < 8; ++it) {
        int idx = tid + it * 256;
        int m = idx >> 5;
        int k4 = (idx & 31) << 2;
        float4 v = make_float4(0.f, 0.f, 0.f, 0.f);
        int gr = gm + m;
        if (gr < M) v = *(const float4*)(A + (size_t)gr * H + k4);
        uint32_t h0, l0, h1, l1;
        split2(v.x, v.y, h0, l0);
        split2(v.z, v.w, h1, l1);
        uint32_t off = (uint32_t)m * ASTRIDE + (uint32_t)k4 * 2;
        *(uint2*)(sm + SM_AH + off) = make_uint2(h0, h1);
        *(uint2*)(sm + SM_AL + off) = make_uint2(l0, l1);
    }
}
__device__ __forceinline__ void fetch_A(const float* __restrict__ A, int gm, int M,
                                        float4* v, int tid) {
#pragma unroll
    for (int it = 0; it < 8; ++it) {
        int idx = tid + it * 256;
        int m = idx >> 5;
        int k4 = (idx & 31) << 2;
        int gr = gm + m;
        v[it] = (gr < M) ? *(const float4*)(A + (size_t)gr * H + k4)
                         : make_float4(0.f, 0.f, 0.f, 0.f);
    }
}
__device__ __forceinline__ void store_A(const float4* v, char* sm, int tid) {
#pragma unroll
    for (int it = 0; it < 8; ++it) {
        int idx = tid + it * 256;
        int m = idx >> 5;
        int k4 = (idx & 31) << 2;
        uint32_t h0, l0, h1, l1;
        split2(v[it].x, v[it].y, h0, l0);
        split2(v[it].z, v[it].w, h1, l1);
        uint32_t off = (uint32_t)m * ASTRIDE + (uint32_t)k4 * 2;
        *(uint2*)(sm + SM_AH + off) = make_uint2(h0, h1);
        *(uint2*)(sm + SM_AL + off) = make_uint2(l0, l1);
    }
}
__device__ __forceinline__ void copy_W(const char* __restrict__ wh, const char* __restrict__ wl,
                                       char* sm, int tid) {
#pragma unroll
    for (int it = 0; it < 8; ++it) {
        int idx = tid + it * 256;
        int row = idx >> 4;
        int chunk = idx & 15;
        uint32_t off = (uint32_t)row * ASTRIDE + (uint32_t)chunk * 16;
        *(uint4*)(sm + SM_WH + off) = ((const uint4*)wh)[idx];
        *(uint4*)(sm + SM_WL + off) = ((const uint4*)wl)[idx];
    }
}

// 3-term compensated HMMA with fragment reuse:
// per kf: 8 ldsm (Ah,Al,Wh,Wl once each), 24 MMAs (Ah*Wh, Ah*Wl, Al*Wh)
__device__ __forceinline__ void gemm_hmma(uint32_t sb, int wm, int wn, int lane,
                                          float acc[2][4][4]) {
    uint32_t aRowBase = (uint32_t)(wm * 32 + (lane & 15)) * ASTRIDE + (uint32_t)(lane >> 4) * 16;
    uint32_t bRowBase = (uint32_t)(wn * 32 + (lane & 15)) * ASTRIDE + (uint32_t)(lane >> 4) * 16;
    uint32_t ahB = sb + SM_AH + aRowBase;
    uint32_t alB = sb + SM_AL + aRowBase;
    uint32_t whB = sb + SM_WH + bRowBase;
    uint32_t wlB = sb + SM_WL + bRowBase;
#pragma unroll
    for (int kf = 0; kf < 8; ++kf) {
        uint32_t ah[2][4], al[2][4], wh[2][4], wl[2][4];
#pragma unroll
        for (int mf = 0; mf < 2; ++mf) {
            ldsm_x4(ah[mf], ahB + mf * 16 * ASTRIDE + kf * 32);
            ldsm_x4(al[mf], alB + mf * 16 * ASTRIDE + kf * 32);
        }
#pragma unroll
        for (int p = 0; p < 2; ++p) {
            ldsm_x4(wh[p], whB + p * 16 * ASTRIDE + kf * 32);
            ldsm_x4(wl[p], wlB + p * 16 * ASTRIDE + kf * 32);
        }
#pragma unroll
        for (int mf = 0; mf < 2; ++mf) {
            // term 1: Ah * Wh
            mma16816(acc[mf][0], ah[mf], wh[0][0], wh[0][2]);
            mma16816(acc[mf][1], ah[mf], wh[0][1], wh[0][3]);
            mma16816(acc[mf][2], ah[mf], wh[1][0], wh[1][2]);
            mma16816(acc[mf][3], ah[mf], wh[1][1], wh[1][3]);
            // term 2: Ah * Wl
            mma16816(acc[mf][0], ah[mf], wl[0][0], wl[0][2]);
            mma16816(acc[mf][1], ah[mf], wl[0][1], wl[0][3]);
            mma16816(acc[mf][2], ah[mf], wl[1][0], wl[1][2]);
            mma16816(acc[mf][3], ah[mf], wl[1][1], wl[1][3]);
            // term 3: Al * Wh
            mma16816(acc[mf][0], al[mf], wh[0][0], wh[0][2]);
            mma16816(acc[mf][1], al[mf], wh[0][1], wh[0][3]);
            mma16816(acc[mf][2], al[mf], wh[1][0], wh[1][2]);
            mma16816(acc[mf][3], al[mf], wh[1][1], wh[1][3]);
        }
    }
}

// ---------------- launch 0: zero buffers ----------------
__global__ void prep_zero(float* __restrict__ hs, int* __restrict__ cnt, int nh, int nd) {
    int i = blockIdx.x * blockDim.x + threadIdx.x;
    if (i < nh) hs[i] = 0.f;
    if (i < nd) cnt[i] = 0;
}

// ---------------- launch 1: idx convert (per-block dtype sniff) + weight prep ----------------
__device__ __forceinline__ void split_store_w(int t, int n, int k4,
                                              float v0, float v1, float v2, float v3) {
    uint32_t h0, l0, h1, l1;
    split2(v0, v1, h0, l0);
    split2(v2, v3, h1, l1);
    uint32_t off = (uint32_t)n * 256 + (uint32_t)k4 * 2;
    *(uint2*)(g_Wimg + (size_t)t * 32768 + off)       = make_uint2(h0, h1);
    *(uint2*)(g_Wimg + (size_t)(7 + t) * 32768 + off) = make_uint2(l0, l1);
}

__global__ void prep_idx_w(const void* __restrict__ ei, int E, int N, int cBlocks,
                           int* __restrict__ row, int* __restrict__ col,
                           int* __restrict__ cnt,
                           const float* __restrict__ We1, const float* __restrict__ We2,
                           const float* __restrict__ Wn1, const float* __restrict__ Wn2) {
    int tid = threadIdx.x;
    if ((int)blockIdx.x < cBlocks) {
        const long long* p64 = (const long long*)ei;
        long long sv = p64[tid];
        int not64 = __syncthreads_or((sv < 0) | (sv >= (long long)N));
        int e = blockIdx.x * 256 + tid;
        if (e < E) {
            int r, c;
            if (not64) {
                const int* p = (const int*)ei;
                r = p[e]; c = p[E + e];
            } else {
                r = (int)p64[e]; c = (int)p64[(size_t)E + e];
            }
            r = min(max(r, 0), N - 1);
            c = min(max(c, 0), N - 1);
            row[e] = r;
            col[e] = c;
            atomicAdd(&cnt[c], 1);
        }
    } else {
        int task = ((int)blockIdx.x - cBlocks) * 256 + tid;
        if (task >= 7 * 4096) return;
        int t = task >> 12;
        int r = task & 4095;
        int n = r >> 5;
        int k4 = (r & 31) << 2;
        const float* src;
        switch (t) {
            case 0: src = We1;          break;
            case 1: src = We1 + 16384;  break;
            case 2: src = We1 + 32768;  break;
            case 3: src = We2;          break;
            case 4: src = Wn1;          break;
            case 5: src = Wn1 + 16384;  break;
            default: src = Wn2;         break;
        }
        split_store_w(t, n, k4,
                      src[(k4 + 0) * H + n], src[(k4 + 1) * H + n],
                      src[(k4 + 2) * H + n], src[(k4 + 3) * H + n]);
    }
}

// ---------------- launch 2: fused P & Q GEMM ----------------
__global__ void __launch_bounds__(256, 2)
node_pq(const float* __restrict__ x,
        const char* __restrict__ w0h, const char* __restrict__ w0l,
        const char* __restrict__ w1h, const char* __restrict__ w1l,
        const float* __restrict__ be1,
        float* __restrict__ P, float* __restrict__ Q, int M) {
    extern __shared__ char sm[];
    uint32_t sb = smem_u32(sm);
    int tid = threadIdx.x, lane = tid & 31, wid = tid >> 5;
    int wm = wid & 1, wn = wid >> 1;
    int gm = blockIdx.x * BM;
    bool isQ = (blockIdx.y != 0);
    const char* wh = isQ ? w1h : w0h;
    const char* wl = isQ ? w1l : w0l;
    float* C = isQ ? Q : P;

    float acc[2][4][4];
#pragma unroll
    for (int a = 0; a < 2; ++a)
#pragma unroll
        for (int b = 0; b < 4; ++b)
#pragma unroll
            for (int c = 0; c < 4; ++c) acc[a][b][c] = 0.f;

    load_convert_A(x, gm, M, sm, tid);
    copy_W(wh, wl, sm, tid);
    __syncthreads();
    gemm_hmma(sb, wm, wn, lane, acc);

    int gid = lane >> 2, tig = lane & 3;
#pragma unroll
    for (int mf = 0; mf < 2; ++mf) {
        int r0 = gm + wm * 32 + mf * 16 + gid;
        int r1 = r0 + 8;
#pragma unroll
        for (int nf = 0; nf < 4; ++nf) {
            int c = wn * 32 + nf * 8 + tig * 2;
            float bx = 0.f, by = 0.f;
            if (!isQ) {
                float2 b = *(const float2*)(be1 + c);
                bx = b.x; by = b.y;
            }
            if (r0 < M)
                *(float2*)(C + (size_t)r0 * H + c) =
                    make_float2(acc[mf][nf][0] + bx, acc[mf][nf][1] + by);
            if (r1 < M)
                *(float2*)(C + (size_t)r1 * H + c) =
                    make_float2(acc[mf][nf][2] + bx, acc[mf][nf][3] + by);
        }
    }
}

// ---------------- launch 3: persistent edge GEMM -> R ----------------
__global__ void __launch_bounds__(256, 2)
edge_gemm(const float* __restrict__ EA, const char* __restrict__ wh, const char* __restrict__ wl,
          float* __restrict__ Rg, int E, int nTiles) {
    extern __shared__ char sm[];
    uint32_t sb = smem_u32(sm);
    int tid = threadIdx.x, lane = tid & 31, wid = tid >> 5;
    int wm = wid & 1, wn = wid >> 1;
    int gid = lane >> 2, tig = lane & 3;

    copy_W(wh, wl, sm, tid);

    int t = blockIdx.x;
    float4 av[8];
    if (t < nTiles) fetch_A(EA, t * BM, E, av, tid);

    for (; t < nTiles; t += gridDim.x) {
        int ge = t * BM;
        int tn = t + gridDim.x;

        store_A(av, sm, tid);
        __syncthreads();

        float acc[2][4][4];
#pragma unroll
        for (int a = 0; a < 2; ++a)
#pragma unroll
            for (int b = 0; b < 4; ++b)
#pragma unroll
                for (int c = 0; c < 4; ++c) acc[a][b][c] = 0.f;
        gemm_hmma(sb, wm, wn, lane, acc);

        if (tn < nTiles) fetch_A(EA, tn * BM, E, av, tid);

#pragma unroll
        for (int mf = 0; mf < 2; ++mf) {
            int r0 = ge + wm * 32 + mf * 16 + gid;
            int r1 = r0 + 8;
#pragma unroll
            for (int nf = 0; nf < 4; ++nf) {
                int c = wn * 32 + nf * 8 + tig * 2;
                if (r0 < E)
                    *(float2*)(Rg + (size_t)r0 * H + c) = make_float2(acc[mf][nf][0], acc[mf][nf][1]);
                if (r1 < E)
                    *(float2*)(Rg + (size_t)r1 * H + c) = make_float2(acc[mf][nf][2], acc[mf][nf][3]);
            }
        }
        __syncthreads();
    }
}

// ---------------- launch 4: edge scatter (full occupancy) ----------------
__global__ void __launch_bounds__(256)
edge_scatter(const float* __restrict__ Rg,
             const int* __restrict__ rowi, const int* __restrict__ coli,
             const float* __restrict__ P, const float* __restrict__ Q,
             float* __restrict__ Hsum, int E) {
    int e = (blockIdx.x * 256 + threadIdx.x) >> 5;
    int lane = threadIdx.x & 31;
    if (e >= E) return;
    int r = rowi[e], c = coli[e];
    int cb = lane * 4;
    float4 rv = *(const float4*)(Rg + (size_t)e * H + cb);
    float4 pv = *(const float4*)(P + (size_t)r * H + cb);
    float4 qv = *(const float4*)(Q + (size_t)c * H + cb);
    float4 v;
    v.x = fmaxf(rv.x + pv.x + qv.x, 0.f);
    v.y = fmaxf(rv.y + pv.y + qv.y, 0.f);
    v.z = fmaxf(rv.z + pv.z + qv.z, 0.f);
    v.w = fmaxf(rv.w + pv.w + qv.w, 0.f);
    red_add_v4(Hsum + (size_t)c * H + cb, v);
}

// ---------------- launches 5-7: node GEMMs ----------------
template<bool DUAL, bool RELU, int BIAS_MODE>
__global__ void __launch_bounds__(256, 2)
node_gemm(const float* __restrict__ A1, const char* __restrict__ w1h, const char* __restrict__ w1l,
          const float* __restrict__ A2, const char* __restrict__ w2h, const char* __restrict__ w2l,
          const float* __restrict__ bias, const int* __restrict__ cnt,
          float* __restrict__ C, int M) {
    extern __shared__ char sm[];
    uint32_t sb = smem_u32(sm);
    int tid = threadIdx.x, lane = tid & 31, wid = tid >> 5;
    int wm = wid & 1, wn = wid >> 1;
    int gm = blockIdx.x * BM;

    float acc[2][4][4];
#pragma unroll
    for (int a = 0; a < 2; ++a)
#pragma unroll
        for (int b = 0; b < 4; ++b)
#pragma unroll
            for (int c = 0; c < 4; ++c) acc[a][b][c] = 0.f;

    load_convert_A(A1, gm, M, sm, tid);
    copy_W(w1h, w1l, sm, tid);
    __syncthreads();
    gemm_hmma(sb, wm, wn, lane, acc);
    if (DUAL) {
        __syncthreads();
        load_convert_A(A2, gm, M, sm, tid);
        copy_W(w2h, w2l, sm, tid);
        __syncthreads();
        gemm_hmma(sb, wm, wn, lane, acc);
    }

    int gid = lane >> 2, tig = lane & 3;
#pragma unroll
    for (int mf = 0; mf < 2; ++mf) {
        int r0 = gm + wm * 32 + mf * 16 + gid;
        int r1 = r0 + 8;
        float d0 = 0.f, d1 = 0.f;
        if (BIAS_MODE == 2) {
            if (r0 < M) d0 = (float)cnt[r0];
            if (r1 < M) d1 = (float)cnt[r1];
        }
#pragma unroll
        for (int nf = 0; nf < 4; ++nf) {
            int c = wn * 32 + nf * 8 + tig * 2;
            float bx = 0.f, by = 0.f;
            if (BIAS_MODE != 0) {
                float2 b = *(const float2*)(bias + c);
                bx = b.x; by = b.y;
            }
            if (r0 < M) {
                float vx = acc[mf][nf][0], vy = acc[mf][nf][1];
                if (BIAS_MODE == 1) { vx += bx; vy += by; }
                else if (BIAS_MODE == 2) { vx += d0 * bx; vy += d0 * by; }
                if (RELU) { vx = fmaxf(vx, 0.f); vy = fmaxf(vy, 0.f); }
                *(float2*)(C + (size_t)r0 * H + c) = make_float2(vx, vy);
            }
            if (r1 < M) {
                float vx = acc[mf][nf][2], vy = acc[mf][nf][3];
                if (BIAS_MODE == 1) { vx += bx; vy += by; }
                else if (BIAS_MODE == 2) { vx += d1 * bx; vy += d1 * by; }
                if (RELU) { vx = fmaxf(vx, 0.f); vy = fmaxf(vy, 0.f); }
                *(float2*)(C + (size_t)r1 * H + c) = make_float2(vx, vy);
            }
        }
    }
}

// ---------------- host ----------------
extern "C" void kernel_launch(void* const* d_in, const int* in_sizes, int n_in,
                              void* d_out, int out_size) {
    const float* x   = (const float*)d_in[0];
    const void*  ei  = d_in[1];
    const float* ea  = (const float*)d_in[2];
    const float* We1 = (const float*)d_in[3];
    const float* be1 = (const float*)d_in[4];
    const float* We2 = (const float*)d_in[5];
    const float* be2 = (const float*)d_in[6];
    const float* Wn1 = (const float*)d_in[7];
    const float* bn1 = (const float*)d_in[8];
    const float* Wn2 = (const float*)d_in[9];
    const float* bn2 = (const float*)d_in[10];
    float* out = (float*)d_out;

    int N = in_sizes[0] / H;
    int E = in_sizes[1] / 2;

    void *pP, *pQ, *pHs, *pAgg, *pT, *pR, *pCnt, *pRow, *pCol, *pWimg;
    cudaGetSymbolAddress(&pP, g_P);
    cudaGetSymbolAddress(&pQ, g_Q);
    cudaGetSymbolAddress(&pHs, g_Hsum);
    cudaGetSymbolAddress(&pAgg, g_agg);
    cudaGetSymbolAddress(&pT, g_Tbuf);
    cudaGetSymbolAddress(&pR, g_R);
    cudaGetSymbolAddress(&pCnt, g_cnt);
    cudaGetSymbolAddress(&pRow, g_row);
    cudaGetSymbolAddress(&pCol, g_col);
    cudaGetSymbolAddress(&pWimg, g_Wimg);
    float* P   = (float*)pP;
    float* Q   = (float*)pQ;
    float* Hs  = (float*)pHs;
    float* agg = (float*)pAgg;
    float* T   = (float*)pT;
    float* Rg  = (float*)pR;
    int*   cnt = (int*)pCnt;
    int*   ro  = (int*)pRow;
    int*   co  = (int*)pCol;
    const char* W = (const char*)pWimg;
    auto wH = [&](int t) { return W + (size_t)t * 32768; };
    auto wL = [&](int t) { return W + (size_t)(7 + t) * 32768; };

    cudaFuncSetAttribute(node_pq, cudaFuncAttributeMaxDynamicSharedMemorySize, SMEM_GEMM);
    cudaFuncSetAttribute(edge_gemm, cudaFuncAttributeMaxDynamicSharedMemorySize, SMEM_GEMM);
    cudaFuncSetAttribute(node_gemm<false, false, 1>, cudaFuncAttributeMaxDynamicSharedMemorySize, SMEM_GEMM);
    cudaFuncSetAttribute(node_gemm<false, false, 2>, cudaFuncAttributeMaxDynamicSharedMemorySize, SMEM_GEMM);
    cudaFuncSetAttribute(node_gemm<true,  true,  1>, cudaFuncAttributeMaxDynamicSharedMemorySize, SMEM_GEMM);

    int nodeBlocks = (N + BM - 1) / BM;
    int nTiles = (E + BM - 1) / BM;
    int nh = N * H;
    int cBlocks = (E + 255) / 256;
    int persistCTAs = 148 * 2;
    int scatBlocks = (E * 32 + 255) / 256;

    prep_zero<<<(nh + 255) / 256, 256>>>(Hs, cnt, nh, N);
    prep_idx_w<<<cBlocks + 112, 256>>>(ei, E, N, cBlocks, ro, co, cnt, We1, We2, Wn1, Wn2);
    node_pq<<<dim3(nodeBlocks, 2), 256, SMEM_GEMM>>>(x, wH(0), wL(0), wH(1), wL(1), be1, P, Q, N);
    edge_gemm<<<persistCTAs, 256, SMEM_GEMM>>>(ea, wH(2), wL(2), Rg, E, nTiles);
    edge_scatter<<<scatBlocks, 256>>>(Rg, ro, co, P, Q, Hs, E);
    node_gemm<false, false, 2><<<nodeBlocks, 256, SMEM_GEMM>>>(Hs, wH(3), wL(3), nullptr, nullptr, nullptr, be2, cnt, agg, N);
    node_gemm<true, true, 1><<<nodeBlocks, 256, SMEM_GEMM>>>(x, wH(4), wL(4), agg, wH(5), wL(5), bn1, nullptr, T, N);
    node_gemm<false, false, 1><<<nodeBlocks, 256, SMEM_GEMM>>>(T, wH(6), wL(6), nullptr, nullptr, nullptr, bn2, nullptr, out, N);
}

// round 16
// speedup vs baseline: 1.6222x; 1.1640x over previous
#include <cuda_runtime.h>
#include <cuda_bf16.h>
#include <cstdint>

#define H 128
#define BM 64
#define MAXN 50176
#define MAXE 800000

// ---------------- scratch (device globals) ----------------
__device__ float g_P[MAXN * H];
__device__ float g_Q[MAXN * H];
__device__ float g_Hsum[MAXN * H];
__device__ float g_agg[MAXN * H];
__device__ float g_Tbuf[MAXN * H];
__device__ float g_R[MAXE * H];      // edge GEMM result
__device__ int   g_cnt[MAXN];
__device__ int   g_scan[MAXN];
__device__ int   g_bsum[256];
__device__ int   g_start[MAXN];      // cursors; post-sort = segment end offsets
__device__ int   g_row[MAXE];
__device__ int   g_col[MAXE];
__device__ int2  g_sorted[MAXE];     // {edge id, row[edge]} sorted by col
__device__ __align__(16) char g_Wimg[14 * 32768];

// ---------------- smem layout ----------------
#define ASTRIDE 272
#define ATILE   (64 * ASTRIDE)           // 17408
#define WTILE   (128 * ASTRIDE)          // 34816
#define SM_AH   0
#define SM_AL   ATILE
#define SM_WH   (2 * ATILE)
#define SM_WL   (2 * ATILE + WTILE)
#define SMEM_GEMM (2 * ATILE + 2 * WTILE)        // 104448

// ---------------- PTX helpers ----------------
__device__ __forceinline__ uint32_t smem_u32(const void* p) {
    uint32_t a;
    asm("{ .reg .u64 t; cvta.to.shared.u64 t, %1; cvt.u32.u64 %0, t; }" : "=r"(a) : "l"(p));
    return a;
}
__device__ __forceinline__ void ldsm_x4(uint32_t* r, uint32_t addr) {
    asm volatile("ldmatrix.sync.aligned.m8n8.x4.shared.b16 {%0,%1,%2,%3}, [%4];"
                 : "=r"(r[0]), "=r"(r[1]), "=r"(r[2]), "=r"(r[3]) : "r"(addr));
}
__device__ __forceinline__ void mma16816(float* d, const uint32_t* a, uint32_t b0, uint32_t b1) {
    asm volatile("mma.sync.aligned.m16n8k16.row.col.f32.bf16.bf16.f32 "
                 "{%0,%1,%2,%3}, {%4,%5,%6,%7}, {%8,%9}, {%0,%1,%2,%3};"
                 : "+f"(d[0]), "+f"(d[1]), "+f"(d[2]), "+f"(d[3])
                 : "r"(a[0]), "r"(a[1]), "r"(a[2]), "r"(a[3]), "r"(b0), "r"(b1));
}

// packed fp32x2 -> bf16x2 (lo half = first arg)
__device__ __forceinline__ uint32_t pack_bf16x2(float a, float b) {
    uint32_t r;
    asm("cvt.rn.bf16x2.f32 %0, %1, %2;" : "=r"(r) : "f"(b), "f"(a));
    return r;
}
// split (a,b) into hi bf16x2 + lo bf16x2 (residual)
__device__ __forceinline__ void split2(float a, float b, uint32_t& hi, uint32_t& lo) {
    hi = pack_bf16x2(a, b);
    float fa = __uint_as_float(hi << 16);
    float fb = __uint_as_float(hi & 0xffff0000u);
    lo = pack_bf16x2(a - fa, b - fb);
}

// ---------------- A/W loaders (256 threads) ----------------
__device__ __forceinline__ void load_convert_A(const float* __restrict__ A, int gm, int M,
                                               char* sm, int tid) {
#pragma unroll
    for (int it = 0; it < 8; ++it) {
        int idx = tid + it * 256;
        int m = idx >> 5;
        int k4 = (idx & 31) << 2;
        float4 v = make_float4(0.f, 0.f, 0.f, 0.f);
        int gr = gm + m;
        if (gr < M) v = *(const float4*)(A + (size_t)gr * H + k4);
        uint32_t h0, l0, h1, l1;
        split2(v.x, v.y, h0, l0);
        split2(v.z, v.w, h1, l1);
        uint32_t off = (uint32_t)m * ASTRIDE + (uint32_t)k4 * 2;
        *(uint2*)(sm + SM_AH + off) = make_uint2(h0, h1);
        *(uint2*)(sm + SM_AL + off) = make_uint2(l0, l1);
    }
}
__device__ __forceinline__ void fetch_A(const float* __restrict__ A, int gm, int M,
                                        float4* v, int tid) {
#pragma unroll
    for (int it = 0; it < 8; ++it) {
        int idx = tid + it * 256;
        int m = idx >> 5;
        int k4 = (idx & 31) << 2;
        int gr = gm + m;
        v[it] = (gr < M) ? *(const float4*)(A + (size_t)gr * H + k4)
                         : make_float4(0.f, 0.f, 0.f, 0.f);
    }
}
__device__ __forceinline__ void store_A(const float4* v, char* sm, int tid) {
#pragma unroll
    for (int it = 0; it < 8; ++it) {
        int idx = tid + it * 256;
        int m = idx >> 5;
        int k4 = (idx & 31) << 2;
        uint32_t h0, l0, h1, l1;
        split2(v[it].x, v[it].y, h0, l0);
        split2(v[it].z, v[it].w, h1, l1);
        uint32_t off = (uint32_t)m * ASTRIDE + (uint32_t)k4 * 2;
        *(uint2*)(sm + SM_AH + off) = make_uint2(h0, h1);
        *(uint2*)(sm + SM_AL + off) = make_uint2(l0, l1);
    }
}
__device__ __forceinline__ void copy_W(const char* __restrict__ wh, const char* __restrict__ wl,
                                       char* sm, int tid) {
#pragma unroll
    for (int it = 0; it < 8; ++it) {
        int idx = tid + it * 256;
        int row = idx >> 4;
        int chunk = idx & 15;
        uint32_t off = (uint32_t)row * ASTRIDE + (uint32_t)chunk * 16;
        *(uint4*)(sm + SM_WH + off) = ((const uint4*)wh)[idx];
        *(uint4*)(sm + SM_WL + off) = ((const uint4*)wl)[idx];
    }
}

// 3-term compensated HMMA with fragment reuse (8 ldsm, 24 MMA per kf)
__device__ __forceinline__ void gemm_hmma(uint32_t sb, int wm, int wn, int lane,
                                          float acc[2][4][4]) {
    uint32_t aRowBase = (uint32_t)(wm * 32 + (lane & 15)) * ASTRIDE + (uint32_t)(lane >> 4) * 16;
    uint32_t bRowBase = (uint32_t)(wn * 32 + (lane & 15)) * ASTRIDE + (uint32_t)(lane >> 4) * 16;
    uint32_t ahB = sb + SM_AH + aRowBase;
    uint32_t alB = sb + SM_AL + aRowBase;
    uint32_t whB = sb + SM_WH + bRowBase;
    uint32_t wlB = sb + SM_WL + bRowBase;
#pragma unroll
    for (int kf = 0; kf < 8; ++kf) {
        uint32_t ah[2][4], al[2][4], wh[2][4], wl[2][4];
#pragma unroll
        for (int mf = 0; mf < 2; ++mf) {
            ldsm_x4(ah[mf], ahB + mf * 16 * ASTRIDE + kf * 32);
            ldsm_x4(al[mf], alB + mf * 16 * ASTRIDE + kf * 32);
        }
#pragma unroll
        for (int p = 0; p < 2; ++p) {
            ldsm_x4(wh[p], whB + p * 16 * ASTRIDE + kf * 32);
            ldsm_x4(wl[p], wlB + p * 16 * ASTRIDE + kf * 32);
        }
#pragma unroll
        for (int mf = 0; mf < 2; ++mf) {
            mma16816(acc[mf][0], ah[mf], wh[0][0], wh[0][2]);
            mma16816(acc[mf][1], ah[mf], wh[0][1], wh[0][3]);
            mma16816(acc[mf][2], ah[mf], wh[1][0], wh[1][2]);
            mma16816(acc[mf][3], ah[mf], wh[1][1], wh[1][3]);
            mma16816(acc[mf][0], ah[mf], wl[0][0], wl[0][2]);
            mma16816(acc[mf][1], ah[mf], wl[0][1], wl[0][3]);
            mma16816(acc[mf][2], ah[mf], wl[1][0], wl[1][2]);
            mma16816(acc[mf][3], ah[mf], wl[1][1], wl[1][3]);
            mma16816(acc[mf][0], al[mf], wh[0][0], wh[0][2]);
            mma16816(acc[mf][1], al[mf], wh[0][1], wh[0][3]);
            mma16816(acc[mf][2], al[mf], wh[1][0], wh[1][2]);
            mma16816(acc[mf][3], al[mf], wh[1][1], wh[1][3]);
        }
    }
}

// ---------------- launch 0: zero degree histogram ----------------
__global__ void prep_zero(int* __restrict__ cnt, int nd) {
    int i = blockIdx.x * blockDim.x + threadIdx.x;
    if (i < nd) cnt[i] = 0;
}

// ---------------- launch 1: idx convert (per-block dtype sniff) + weight prep ----------------
__device__ __forceinline__ void split_store_w(int t, int n, int k4,
                                              float v0, float v1, float v2, float v3) {
    uint32_t h0, l0, h1, l1;
    split2(v0, v1, h0, l0);
    split2(v2, v3, h1, l1);
    uint32_t off = (uint32_t)n * 256 + (uint32_t)k4 * 2;
    *(uint2*)(g_Wimg + (size_t)t * 32768 + off)       = make_uint2(h0, h1);
    *(uint2*)(g_Wimg + (size_t)(7 + t) * 32768 + off) = make_uint2(l0, l1);
}

__global__ void prep_idx_w(const void* __restrict__ ei, int E, int N, int cBlocks,
                           int* __restrict__ row, int* __restrict__ col,
                           int* __restrict__ cnt,
                           const float* __restrict__ We1, const float* __restrict__ We2,
                           const float* __restrict__ Wn1, const float* __restrict__ Wn2) {
    int tid = threadIdx.x;
    if ((int)blockIdx.x < cBlocks) {
        const long long* p64 = (const long long*)ei;
        long long sv = p64[tid];
        int not64 = __syncthreads_or((sv < 0) | (sv >= (long long)N));
        int e = blockIdx.x * 256 + tid;
        if (e < E) {
            int r, c;
            if (not64) {
                const int* p = (const int*)ei;
                r = p[e]; c = p[E + e];
            } else {
                r = (int)p64[e]; c = (int)p64[(size_t)E + e];
            }
            r = min(max(r, 0), N - 1);
            c = min(max(c, 0), N - 1);
            row[e] = r;
            col[e] = c;
            atomicAdd(&cnt[c], 1);
        }
    } else {
        int task = ((int)blockIdx.x - cBlocks) * 256 + tid;
        if (task >= 7 * 4096) return;
        int t = task >> 12;
        int r = task & 4095;
        int n = r >> 5;
        int k4 = (r & 31) << 2;
        const float* src;
        switch (t) {
            case 0: src = We1;          break;
            case 1: src = We1 + 16384;  break;
            case 2: src = We1 + 32768;  break;
            case 3: src = We2;          break;
            case 4: src = Wn1;          break;
            case 5: src = Wn1 + 16384;  break;
            default: src = Wn2;         break;
        }
        split_store_w(t, n, k4,
                      src[(k4 + 0) * H + n], src[(k4 + 1) * H + n],
                      src[(k4 + 2) * H + n], src[(k4 + 3) * H + n]);
    }
}

// ---------------- launch 2: fused P & Q GEMM ----------------
__global__ void __launch_bounds__(256, 2)
node_pq(const float* __restrict__ x,
        const char* __restrict__ w0h, const char* __restrict__ w0l,
        const char* __restrict__ w1h, const char* __restrict__ w1l,
        const float* __restrict__ be1,
        float* __restrict__ P, float* __restrict__ Q, int M) {
    extern __shared__ char sm[];
    uint32_t sb = smem_u32(sm);
    int tid = threadIdx.x, lane = tid & 31, wid = tid >> 5;
    int wm = wid & 1, wn = wid >> 1;
    int gm = blockIdx.x * BM;
    bool isQ = (blockIdx.y != 0);
    const char* wh = isQ ? w1h : w0h;
    const char* wl = isQ ? w1l : w0l;
    float* C = isQ ? Q : P;

    float acc[2][4][4];
#pragma unroll
    for (int a = 0; a < 2; ++a)
#pragma unroll
        for (int b = 0; b < 4; ++b)
#pragma unroll
            for (int c = 0; c < 4; ++c) acc[a][b][c] = 0.f;

    load_convert_A(x, gm, M, sm, tid);
    copy_W(wh, wl, sm, tid);
    __syncthreads();
    gemm_hmma(sb, wm, wn, lane, acc);

    int gid = lane >> 2, tig = lane & 3;
#pragma unroll
    for (int mf = 0; mf < 2; ++mf) {
        int r0 = gm + wm * 32 + mf * 16 + gid;
        int r1 = r0 + 8;
#pragma unroll
        for (int nf = 0; nf < 4; ++nf) {
            int c = wn * 32 + nf * 8 + tig * 2;
            float bx = 0.f, by = 0.f;
            if (!isQ) {
                float2 b = *(const float2*)(be1 + c);
                bx = b.x; by = b.y;
            }
            if (r0 < M)
                *(float2*)(C + (size_t)r0 * H + c) =
                    make_float2(acc[mf][nf][0] + bx, acc[mf][nf][1] + by);
            if (r1 < M)
                *(float2*)(C + (size_t)r1 * H + c) =
                    make_float2(acc[mf][nf][2] + bx, acc[mf][nf][3] + by);
        }
    }
}

// ---------------- launch 3 (ncu slot): persistent edge GEMM -> R ----------------
__global__ void __launch_bounds__(256, 2)
edge_gemm(const float* __restrict__ EA, const char* __restrict__ wh, const char* __restrict__ wl,
          float* __restrict__ Rg, int E, int nTiles) {
    extern __shared__ char sm[];
    uint32_t sb = smem_u32(sm);
    int tid = threadIdx.x, lane = tid & 31, wid = tid >> 5;
    int wm = wid & 1, wn = wid >> 1;
    int gid = lane >> 2, tig = lane & 3;

    copy_W(wh, wl, sm, tid);

    int t = blockIdx.x;
    float4 av[8];
    if (t < nTiles) fetch_A(EA, t * BM, E, av, tid);

    for (; t < nTiles; t += gridDim.x) {
        int ge = t * BM;
        int tn = t + gridDim.x;

        store_A(av, sm, tid);                  // consumes av
        __syncthreads();

        // prefetch next tile BEFORE the long MMA body -> LDG latency fully hidden
        if (tn < nTiles) fetch_A(EA, tn * BM, E, av, tid);

        float acc[2][4][4];
#pragma unroll
        for (int a = 0; a < 2; ++a)
#pragma unroll
            for (int b = 0; b < 4; ++b)
#pragma unroll
                for (int c = 0; c < 4; ++c) acc[a][b][c] = 0.f;
        gemm_hmma(sb, wm, wn, lane, acc);

#pragma unroll
        for (int mf = 0; mf < 2; ++mf) {
            int r0 = ge + wm * 32 + mf * 16 + gid;
            int r1 = r0 + 8;
#pragma unroll
            for (int nf = 0; nf < 4; ++nf) {
                int c = wn * 32 + nf * 8 + tig * 2;
                if (r0 < E)
                    *(float2*)(Rg + (size_t)r0 * H + c) = make_float2(acc[mf][nf][0], acc[mf][nf][1]);
                if (r1 < E)
                    *(float2*)(Rg + (size_t)r1 * H + c) = make_float2(acc[mf][nf][2], acc[mf][nf][3]);
            }
        }
        __syncthreads();
    }
}

// ---------------- launches 4-7: scan + counting sort (by col) ----------------
__global__ void scan_a(const int* __restrict__ cnt, int* __restrict__ scan,
                       int* __restrict__ bsum, int N) {
    __shared__ int s[256];
    int t = threadIdx.x, i = blockIdx.x * 256 + t;
    int v = (i < N) ? cnt[i] : 0;
    s[t] = v;
    __syncthreads();
    for (int off = 1; off < 256; off <<= 1) {
        int x = (t >= off) ? s[t - off] : 0;
        __syncthreads();
        s[t] += x;
        __syncthreads();
    }
    if (i < N) scan[i] = s[t] - v;
    if (t == 255) bsum[blockIdx.x] = s[255];
}
__global__ void scan_b(int* __restrict__ bsum, int nb) {
    __shared__ int s[256];
    int t = threadIdx.x;
    int v = (t < nb) ? bsum[t] : 0;
    s[t] = v;
    __syncthreads();
    for (int off = 1; off < 256; off <<= 1) {
        int x = (t >= off) ? s[t - off] : 0;
        __syncthreads();
        s[t] += x;
        __syncthreads();
    }
    if (t < nb) bsum[t] = s[t] - v;
}
__global__ void scan_c(const int* __restrict__ scan, const int* __restrict__ bsum,
                       int* __restrict__ start, int N) {
    int i = blockIdx.x * blockDim.x + threadIdx.x;
    if (i < N) start[i] = scan[i] + bsum[i >> 8];
}
__global__ void scatter_sort(const int* __restrict__ col, const int* __restrict__ rowi, int E,
                             int* __restrict__ start, int2* __restrict__ sorted) {
    int e = blockIdx.x * blockDim.x + threadIdx.x;
    if (e < E) {
        int p = atomicAdd(&start[col[e]], 1);
        sorted[p] = make_int2(e, rowi[e]);
    }
}

// ---------------- launch 8: CSR aggregation (one warp per node) ----------------
__global__ void __launch_bounds__(256)
node_agg(const float* __restrict__ Rg, const int2* __restrict__ se,
         const int* __restrict__ start, const int* __restrict__ cnt,
         const float* __restrict__ P, const float* __restrict__ Q,
         float* __restrict__ Hsum, int N) {
    int n = (blockIdx.x * 256 + threadIdx.x) >> 5;
    int lane = threadIdx.x & 31;
    if (n >= N) return;
    int end = start[n];                  // post-sort cursor = segment end
    int beg = end - cnt[n];
    int cb = lane * 4;
    float4 q = *(const float4*)(Q + (size_t)n * H + cb);
    float4 a0 = make_float4(0.f, 0.f, 0.f, 0.f);
    float4 a1 = make_float4(0.f, 0.f, 0.f, 0.f);
    int i = beg;
    for (; i + 1 < end; i += 2) {
        int2 e0 = se[i], e1 = se[i + 1];
        float4 r0 = *(const float4*)(Rg + (size_t)e0.x * H + cb);
        float4 p0 = *(const float4*)(P + (size_t)e0.y * H + cb);
        float4 r1 = *(const float4*)(Rg + (size_t)e1.x * H + cb);
        float4 p1 = *(const float4*)(P + (size_t)e1.y * H + cb);
        a0.x += fmaxf(r0.x + p0.x + q.x, 0.f);
        a0.y += fmaxf(r0.y + p0.y + q.y, 0.f);
        a0.z += fmaxf(r0.z + p0.z + q.z, 0.f);
        a0.w += fmaxf(r0.w + p0.w + q.w, 0.f);
        a1.x += fmaxf(r1.x + p1.x + q.x, 0.f);
        a1.y += fmaxf(r1.y + p1.y + q.y, 0.f);
        a1.z += fmaxf(r1.z + p1.z + q.z, 0.f);
        a1.w += fmaxf(r1.w + p1.w + q.w, 0.f);
    }
    if (i < end) {
        int2 e0 = se[i];
        float4 r0 = *(const float4*)(Rg + (size_t)e0.x * H + cb);
        float4 p0 = *(const float4*)(P + (size_t)e0.y * H + cb);
        a0.x += fmaxf(r0.x + p0.x + q.x, 0.f);
        a0.y += fmaxf(r0.y + p0.y + q.y, 0.f);
        a0.z += fmaxf(r0.z + p0.z + q.z, 0.f);
        a0.w += fmaxf(r0.w + p0.w + q.w, 0.f);
    }
    float4 o = make_float4(a0.x + a1.x, a0.y + a1.y, a0.z + a1.z, a0.w + a1.w);
    *(float4*)(Hsum + (size_t)n * H + cb) = o;
}

// ---------------- launches 9-11: node GEMMs ----------------
template<bool DUAL, bool RELU, int BIAS_MODE>
__global__ void __launch_bounds__(256, 2)
node_gemm(const float* __restrict__ A1, const char* __restrict__ w1h, const char* __restrict__ w1l,
          const float* __restrict__ A2, const char* __restrict__ w2h, const char* __restrict__ w2l,
          const float* __restrict__ bias, const int* __restrict__ cnt,
          float* __restrict__ C, int M) {
    extern __shared__ char sm[];
    uint32_t sb = smem_u32(sm);
    int tid = threadIdx.x, lane = tid & 31, wid = tid >> 5;
    int wm = wid & 1, wn = wid >> 1;
    int gm = blockIdx.x * BM;

    float acc[2][4][4];
#pragma unroll
    for (int a = 0; a < 2; ++a)
#pragma unroll
        for (int b = 0; b < 4; ++b)
#pragma unroll
            for (int c = 0; c < 4; ++c) acc[a][b][c] = 0.f;

    load_convert_A(A1, gm, M, sm, tid);
    copy_W(w1h, w1l, sm, tid);
    __syncthreads();
    gemm_hmma(sb, wm, wn, lane, acc);
    if (DUAL) {
        __syncthreads();
        load_convert_A(A2, gm, M, sm, tid);
        copy_W(w2h, w2l, sm, tid);
        __syncthreads();
        gemm_hmma(sb, wm, wn, lane, acc);
    }

    int gid = lane >> 2, tig = lane & 3;
#pragma unroll
    for (int mf = 0; mf < 2; ++mf) {
        int r0 = gm + wm * 32 + mf * 16 + gid;
        int r1 = r0 + 8;
        float d0 = 0.f, d1 = 0.f;
        if (BIAS_MODE == 2) {
            if (r0 < M) d0 = (float)cnt[r0];
            if (r1 < M) d1 = (float)cnt[r1];
        }
#pragma unroll
        for (int nf = 0; nf < 4; ++nf) {
            int c = wn * 32 + nf * 8 + tig * 2;
            float bx = 0.f, by = 0.f;
            if (BIAS_MODE != 0) {
                float2 b = *(const float2*)(bias + c);
                bx = b.x; by = b.y;
            }
            if (r0 < M) {
                float vx = acc[mf][nf][0], vy = acc[mf][nf][1];
                if (BIAS_MODE == 1) { vx += bx; vy += by; }
                else if (BIAS_MODE == 2) { vx += d0 * bx; vy += d0 * by; }
                if (RELU) { vx = fmaxf(vx, 0.f); vy = fmaxf(vy, 0.f); }
                *(float2*)(C + (size_t)r0 * H + c) = make_float2(vx, vy);
            }
            if (r1 < M) {
                float vx = acc[mf][nf][2], vy = acc[mf][nf][3];
                if (BIAS_MODE == 1) { vx += bx; vy += by; }
                else if (BIAS_MODE == 2) { vx += d1 * bx; vy += d1 * by; }
                if (RELU) { vx = fmaxf(vx, 0.f); vy = fmaxf(vy, 0.f); }
                *(float2*)(C + (size_t)r1 * H + c) = make_float2(vx, vy);
            }
        }
    }
}

// ---------------- host ----------------
extern "C" void kernel_launch(void* const* d_in, const int* in_sizes, int n_in,
                              void* d_out, int out_size) {
    const float* x   = (const float*)d_in[0];
    const void*  ei  = d_in[1];
    const float* ea  = (const float*)d_in[2];
    const float* We1 = (const float*)d_in[3];
    const float* be1 = (const float*)d_in[4];
    const float* We2 = (const float*)d_in[5];
    const float* be2 = (const float*)d_in[6];
    const float* Wn1 = (const float*)d_in[7];
    const float* bn1 = (const float*)d_in[8];
    const float* Wn2 = (const float*)d_in[9];
    const float* bn2 = (const float*)d_in[10];
    float* out = (float*)d_out;

    int N = in_sizes[0] / H;
    int E = in_sizes[1] / 2;

    void *pP, *pQ, *pHs, *pAgg, *pT, *pR, *pCnt, *pScan, *pBsum, *pStart, *pRow, *pCol, *pSort, *pWimg;
    cudaGetSymbolAddress(&pP, g_P);
    cudaGetSymbolAddress(&pQ, g_Q);
    cudaGetSymbolAddress(&pHs, g_Hsum);
    cudaGetSymbolAddress(&pAgg, g_agg);
    cudaGetSymbolAddress(&pT, g_Tbuf);
    cudaGetSymbolAddress(&pR, g_R);
    cudaGetSymbolAddress(&pCnt, g_cnt);
    cudaGetSymbolAddress(&pScan, g_scan);
    cudaGetSymbolAddress(&pBsum, g_bsum);
    cudaGetSymbolAddress(&pStart, g_start);
    cudaGetSymbolAddress(&pRow, g_row);
    cudaGetSymbolAddress(&pCol, g_col);
    cudaGetSymbolAddress(&pSort, g_sorted);
    cudaGetSymbolAddress(&pWimg, g_Wimg);
    float* P    = (float*)pP;
    float* Q    = (float*)pQ;
    float* Hs   = (float*)pHs;
    float* agg  = (float*)pAgg;
    float* T    = (float*)pT;
    float* Rg   = (float*)pR;
    int*   cnt  = (int*)pCnt;
    int*   scn  = (int*)pScan;
    int*   bsm  = (int*)pBsum;
    int*   stt  = (int*)pStart;
    int*   ro   = (int*)pRow;
    int*   co   = (int*)pCol;
    int2*  srt  = (int2*)pSort;
    const char* W = (const char*)pWimg;
    auto wH = [&](int t) { return W + (size_t)t * 32768; };
    auto wL = [&](int t) { return W + (size_t)(7 + t) * 32768; };

    cudaFuncSetAttribute(node_pq, cudaFuncAttributeMaxDynamicSharedMemorySize, SMEM_GEMM);
    cudaFuncSetAttribute(edge_gemm, cudaFuncAttributeMaxDynamicSharedMemorySize, SMEM_GEMM);
    cudaFuncSetAttribute(node_gemm<false, false, 1>, cudaFuncAttributeMaxDynamicSharedMemorySize, SMEM_GEMM);
    cudaFuncSetAttribute(node_gemm<false, false, 2>, cudaFuncAttributeMaxDynamicSharedMemorySize, SMEM_GEMM);
    cudaFuncSetAttribute(node_gemm<true,  true,  1>, cudaFuncAttributeMaxDynamicSharedMemorySize, SMEM_GEMM);

    int nodeBlocks = (N + BM - 1) / BM;
    int nTiles = (E + BM - 1) / BM;
    int cBlocks = (E + 255) / 256;
    int scanBlocks = (N + 255) / 256;
    int persistCTAs = 148 * 2;
    int aggBlocks = (N * 32 + 255) / 256;

    // 0: zero degree histogram
    prep_zero<<<scanBlocks, 256>>>(cnt, N);
    // 1: idx convert + weight images
    prep_idx_w<<<cBlocks + 112, 256>>>(ei, E, N, cBlocks, ro, co, cnt, We1, We2, Wn1, Wn2);
    // 2: P = x@We1a + be1 ; Q = x@We1b
    node_pq<<<dim3(nodeBlocks, 2), 256, SMEM_GEMM>>>(x, wH(0), wL(0), wH(1), wL(1), be1, P, Q, N);
    // 3 (ncu slot): pure edge GEMM -> R
    edge_gemm<<<persistCTAs, 256, SMEM_GEMM>>>(ea, wH(2), wL(2), Rg, E, nTiles);
    // 4-7: CSR build (independent of edge_gemm; overlaps in-flight work poorly but cheap)
    scan_a<<<scanBlocks, 256>>>(cnt, scn, bsm, N);
    scan_b<<<1, 256>>>(bsm, scanBlocks);
    scan_c<<<scanBlocks, 256>>>(scn, bsm, stt, N);
    scatter_sort<<<cBlocks, 256>>>(co, ro, E, stt, srt);
    // 8: Hsum[n] = sum over CSR segment of relu(R + P[row] + Q[n])
    node_agg<<<aggBlocks, 256>>>(Rg, srt, stt, cnt, P, Q, Hs, N);
    // 9: agg = Hsum@We2 + deg*be2
    node_gemm<false, false, 2><<<nodeBlocks, 256, SMEM_GEMM>>>(Hs, wH(3), wL(3), nullptr, nullptr, nullptr, be2, cnt, agg, N);
    // 10: T = relu(x@Wn1a + agg@Wn1b + bn1)
    node_gemm<true, true, 1><<<nodeBlocks, 256, SMEM_GEMM>>>(x, wH(4), wL(4), agg, wH(5), wL(5), bn1, nullptr, T, N);
    // 11: out = T@Wn2 + bn2
    node_gemm<false, false, 1><<<nodeBlocks, 256, SMEM_GEMM>>>(T, wH(6), wL(6), nullptr, nullptr, nullptr, bn2, nullptr, out, N);
}